// round 2
// baseline (speedup 1.0000x reference)
#include <cuda_runtime.h>
#include <cuda_bf16.h>
#include <cstdint>
#include <math.h>

// Problem constants
#define B_   128
#define C_   1024
#define R_   256
#define T_   4
#define H_   7
#define W_   7
#define P_   196     // T*H*W
#define EPSV 1e-5f

// ---------------- intermediates (device globals; no allocation allowed) ----
__device__ float g_hmean[B_ * R_];    // mean of hardswish(BN(x·w1^T)) per (b,r)
__device__ float g_coords[B_ * 6];    // sx, sy, st, ex, ey, et per batch

// ---------------- helpers ---------------------------------------------------
__device__ __forceinline__ float tf32r(float v) {
    uint32_t u;
    asm("cvt.rna.tf32.f32 %0, %1;" : "=r"(u) : "f"(v));
    return __uint_as_float(u);
}

__device__ __forceinline__ void mma_tf32(float& d0, float& d1, float& d2, float& d3,
                                         uint32_t a0, uint32_t a1, uint32_t a2, uint32_t a3,
                                         uint32_t b0, uint32_t b1) {
    asm volatile(
        "mma.sync.aligned.m16n8k8.row.col.f32.tf32.tf32.f32 "
        "{%0,%1,%2,%3}, {%4,%5,%6,%7}, {%8,%9}, {%0,%1,%2,%3};\n"
        : "+f"(d0), "+f"(d1), "+f"(d2), "+f"(d3)
        : "r"(a0), "r"(a1), "r"(a2), "r"(a3), "r"(b0), "r"(b1));
}

// ============================================================================
// Kernel A: per-batch GEMM  H[r,p] = sum_c w1[r,c] * x[b,c,p]
// fused BN-affine + hardswish + mean over p  ->  g_hmean[b][r]
//
// One block per batch. 256 threads = 8 warps (4 along M x 2 along N).
// Two N passes of 112 columns (196 real cols, zero-padded).
// K chunked by 32 into smem, tf32 mma.sync m16n8k8, 64x56 warp tile.
// ============================================================================
#define KC      32
#define AW_S    36     // smem stride of w1 tile (conflict-free frag loads)
#define XS_S    120    // smem stride of x tile  (conflict-free frag loads)
#define NPW     112    // N columns per pass

// smem layout (floats):
//  Aw  [256][36]  : 9216
//  Xs  [32][120]  : 3840
//  part[2][256]   : 512
//  sc  [256]      : 256
//  bi  [256]      : 256
#define SM_AW   0
#define SM_XS   9216
#define SM_PART 13056
#define SM_SC   13568
#define SM_BI   13824
#define SM_TOT  14080  // floats -> 56320 bytes

__global__ void __launch_bounds__(256, 1)
kernelA(const float* __restrict__ x, const float* __restrict__ w1,
        const float* __restrict__ g1, const float* __restrict__ b1,
        const float* __restrict__ m1, const float* __restrict__ v1) {
    extern __shared__ float smem[];
    float* Aw   = smem + SM_AW;
    float* Xs   = smem + SM_XS;
    float* part = smem + SM_PART;
    float* sc   = smem + SM_SC;
    float* bi   = smem + SM_BI;

    const int b    = blockIdx.x;
    const int tid  = threadIdx.x;
    const int lane = tid & 31;
    const int warp = tid >> 5;
    const int wm   = warp >> 1;   // 0..3 : M offset wm*64
    const int wn   = warp & 1;    // 0..1 : N offset wn*56

    // zero BOTH halves of the partial-sum buffer (256 threads, 512 entries!)
    part[tid]       = 0.f;
    part[tid + 256] = 0.f;
    if (tid < 256) {
        float s = g1[tid] * rsqrtf(v1[tid] + EPSV);
        sc[tid] = s;
        bi[tid] = b1[tid] - m1[tid] * s;
    }

    const float* xb = x + (size_t)b * C_ * P_;

    #pragma unroll 1
    for (int np = 0; np < 2; np++) {
        float d[4][7][4];
        #pragma unroll
        for (int mt = 0; mt < 4; mt++)
            #pragma unroll
            for (int nt = 0; nt < 7; nt++)
                #pragma unroll
                for (int j = 0; j < 4; j++) d[mt][nt][j] = 0.f;

        #pragma unroll 1
        for (int kc = 0; kc < C_; kc += KC) {
            __syncthreads();
            // load w1 tile [256][32]
            #pragma unroll
            for (int i = 0; i < 32; i++) {
                int idx = i * 256 + tid;
                int row = idx >> 5;
                int col = idx & 31;
                Aw[row * AW_S + col] = tf32r(w1[row * C_ + kc + col]);
            }
            // load x tile [32][112] (zero-pad beyond p=196)
            #pragma unroll
            for (int i = 0; i < 14; i++) {
                int idx = i * 256 + tid;
                int row = idx / NPW;
                int col = idx - row * NPW;
                int p   = np * NPW + col;
                float v = (p < P_) ? xb[(size_t)(kc + row) * P_ + p] : 0.f;
                Xs[row * XS_S + col] = tf32r(v);
            }
            __syncthreads();

            #pragma unroll
            for (int kk = 0; kk < 4; kk++) {
                uint32_t a[4][4];
                const int ar = wm * 64 + (lane >> 2);
                const int ac = kk * 8 + (lane & 3);
                #pragma unroll
                for (int mt = 0; mt < 4; mt++) {
                    a[mt][0] = __float_as_uint(Aw[(ar + mt * 16    ) * AW_S + ac    ]);
                    a[mt][1] = __float_as_uint(Aw[(ar + mt * 16 + 8) * AW_S + ac    ]);
                    a[mt][2] = __float_as_uint(Aw[(ar + mt * 16    ) * AW_S + ac + 4]);
                    a[mt][3] = __float_as_uint(Aw[(ar + mt * 16 + 8) * AW_S + ac + 4]);
                }
                uint32_t bb[7][2];
                const int br = kk * 8 + (lane & 3);
                const int bc = wn * 56 + (lane >> 2);
                #pragma unroll
                for (int nt = 0; nt < 7; nt++) {
                    bb[nt][0] = __float_as_uint(Xs[ br      * XS_S + bc + nt * 8]);
                    bb[nt][1] = __float_as_uint(Xs[(br + 4) * XS_S + bc + nt * 8]);
                }
                #pragma unroll
                for (int mt = 0; mt < 4; mt++)
                    #pragma unroll
                    for (int nt = 0; nt < 7; nt++)
                        mma_tf32(d[mt][nt][0], d[mt][nt][1], d[mt][nt][2], d[mt][nt][3],
                                 a[mt][0], a[mt][1], a[mt][2], a[mt][3],
                                 bb[nt][0], bb[nt][1]);
            }
        }

        // epilogue: BN affine + hardswish + per-row sum over this pass's columns
        const int pbase = np * NPW + wn * 56 + (lane & 3) * 2;
        #pragma unroll
        for (int mt = 0; mt < 4; mt++) {
            const int r0 = wm * 64 + mt * 16 + (lane >> 2);
            const int r1 = r0 + 8;
            const float s0c = sc[r0], b0c = bi[r0];
            const float s1c = sc[r1], b1c = bi[r1];
            float acc0 = 0.f, acc1 = 0.f;
            #pragma unroll
            for (int nt = 0; nt < 7; nt++) {
                #pragma unroll
                for (int jj = 0; jj < 2; jj++) {
                    int p = pbase + nt * 8 + jj;
                    if (p < P_) {
                        float h0 = d[mt][nt][jj] * s0c + b0c;
                        acc0 += h0 * fminf(fmaxf(h0 + 3.f, 0.f), 6.f) * (1.f / 6.f);
                        float h1 = d[mt][nt][2 + jj] * s1c + b1c;
                        acc1 += h1 * fminf(fmaxf(h1 + 3.f, 0.f), 6.f) * (1.f / 6.f);
                    }
                }
            }
            acc0 += __shfl_xor_sync(0xFFFFFFFFu, acc0, 1);
            acc0 += __shfl_xor_sync(0xFFFFFFFFu, acc0, 2);
            acc1 += __shfl_xor_sync(0xFFFFFFFFu, acc1, 1);
            acc1 += __shfl_xor_sync(0xFFFFFFFFu, acc1, 2);
            if ((lane & 3) == 0) {
                part[wn * 256 + r0] += acc0;   // exclusive writer per (wn, r)
                part[wn * 256 + r1] += acc1;
            }
        }
    }

    __syncthreads();
    if (tid < 256)
        g_hmean[b * R_ + tid] = (part[tid] + part[256 + tid]) * (1.f / (float)P_);
}

// ============================================================================
// Kernel B: logits = hmean @ w2^T ; BN2 ; sigmoid ; ROI coords
// one warp per batch
// ============================================================================
__global__ void kernelB(const float* __restrict__ w2, const float* __restrict__ g2,
                        const float* __restrict__ b2, const float* __restrict__ m2,
                        const float* __restrict__ v2) {
    const int b = blockIdx.x;
    const int lane = threadIdx.x;
    const float* h = g_hmean + b * R_;

    float lg[6];
    #pragma unroll
    for (int j = 0; j < 6; j++) {
        float s = 0.f;
        #pragma unroll
        for (int r = lane; r < R_; r += 32) s += h[r] * w2[j * R_ + r];
        #pragma unroll
        for (int off = 16; off; off >>= 1) s += __shfl_xor_sync(0xFFFFFFFFu, s, off);
        lg[j] = s;
    }
    if (lane < 6) {
        const int j = lane;
        float sf = g2[j] * rsqrtf(v2[j] + EPSV);
        float l  = (lg[j] - m2[j]) * sf + b2[j];
        float sig = 1.f / (1.f + expf(-l));
        const float SC[3] = {7.f, 7.f, 4.f};
        float outv = (j < 3) ? (0.5f * sig * SC[j])
                             : ((1.f - 0.5f * sig) * SC[j - 3]);
        g_coords[b * 6 + j] = outv;
    }
}

// ============================================================================
// Kernel C: ROI align 3D. Block = (32-channel tile, batch). 256 threads.
// Stage x[b][ctile][196] in smem, compute 13 axis tables once, 8-tap trilinear.
// out[b][c][ot][oy][ox], out grid 3x5x5 = 75 points.
// ============================================================================
__global__ void __launch_bounds__(256)
kernelC(const float* __restrict__ x, float* __restrict__ out) {
    __shared__ float xs[32 * 200];
    __shared__ int   ilo[13], ihi[13];
    __shared__ float ww0[13], ww1[13];

    const int tid = threadIdx.x;
    const int b   = blockIdx.y;
    const int cc  = blockIdx.x * 32;

    const float* xb = x + ((size_t)b * C_ + cc) * P_;

    // stage channel tile (float4 loads: 196 = 49 * 4, 16B-aligned rows)
    for (int i = tid; i < 32 * 49; i += 256) {
        int c = i / 49, q = i - c * 49;
        float4 v = reinterpret_cast<const float4*>(xb + (size_t)c * P_)[q];
        float* dst = xs + c * 200 + q * 4;
        dst[0] = v.x; dst[1] = v.y; dst[2] = v.z; dst[3] = v.w;
    }

    // axis tables: entries 0..4 = x (size 7, n 5), 5..9 = y (7,5), 10..12 = t (4,3)
    if (tid < 13) {
        int axis = (tid < 5) ? 0 : ((tid < 10) ? 1 : 2);
        int i    = (tid < 5) ? tid : ((tid < 10) ? tid - 5 : tid - 10);
        int   n    = (axis == 2) ? 3 : 5;
        float size = (axis == 2) ? 4.f : 7.f;
        float s = g_coords[b * 6 + axis];
        float e = g_coords[b * 6 + 3 + axis];
        float bin = (e - s) / (float)n;
        float c = s + ((float)i + 0.5f) * bin;
        float valid = (c >= -1.f && c <= size) ? 1.f : 0.f;
        c = fminf(fmaxf(c, 0.f), size - 1.f);
        int lo = (int)floorf(c);
        int hi = min(lo + 1, (int)size - 1);
        float f = c - (float)lo;
        ilo[tid] = lo; ihi[tid] = hi;
        ww0[tid] = (1.f - f) * valid;
        ww1[tid] = f * valid;
    }
    __syncthreads();

    for (int o = tid; o < 32 * 75; o += 256) {
        int c = o / 75, p = o - c * 75;
        int ot = p / 25, r = p - ot * 25;
        int oy = r / 5,  ox = r - oy * 5;

        int t0 = ilo[10 + ot], t1 = ihi[10 + ot];
        float tw0 = ww0[10 + ot], tw1 = ww1[10 + ot];
        int y0 = ilo[5 + oy], y1 = ihi[5 + oy];
        float yw0 = ww0[5 + oy], yw1 = ww1[5 + oy];
        int x0 = ilo[ox], x1 = ihi[ox];
        float xw0 = ww0[ox], xw1 = ww1[ox];

        const float* base = xs + c * 200;
        float v00 = xw0 * base[t0 * 49 + y0 * 7 + x0] + xw1 * base[t0 * 49 + y0 * 7 + x1];
        float v01 = xw0 * base[t0 * 49 + y1 * 7 + x0] + xw1 * base[t0 * 49 + y1 * 7 + x1];
        float v10 = xw0 * base[t1 * 49 + y0 * 7 + x0] + xw1 * base[t1 * 49 + y0 * 7 + x1];
        float v11 = xw0 * base[t1 * 49 + y1 * 7 + x0] + xw1 * base[t1 * 49 + y1 * 7 + x1];
        float v = tw0 * (yw0 * v00 + yw1 * v01) + tw1 * (yw0 * v10 + yw1 * v11);

        out[((size_t)(b * C_ + cc + c)) * 75 + p] = v;
    }
}

// ============================================================================
extern "C" void kernel_launch(void* const* d_in, const int* in_sizes, int n_in,
                              void* d_out, int out_size) {
    const float* x  = (const float*)d_in[0];
    const float* w1 = (const float*)d_in[1];
    const float* g1 = (const float*)d_in[2];
    const float* b1 = (const float*)d_in[3];
    const float* m1 = (const float*)d_in[4];
    const float* v1 = (const float*)d_in[5];
    const float* w2 = (const float*)d_in[6];
    const float* g2 = (const float*)d_in[7];
    const float* b2 = (const float*)d_in[8];
    const float* m2 = (const float*)d_in[9];
    const float* v2 = (const float*)d_in[10];
    float* out = (float*)d_out;

    const size_t smemA = SM_TOT * sizeof(float);  // 56320 B > 48K default
    cudaFuncSetAttribute(kernelA, cudaFuncAttributeMaxDynamicSharedMemorySize, (int)smemA);

    kernelA<<<B_, 256, smemA>>>(x, w1, g1, b1, m1, v1);
    kernelB<<<B_, 32>>>(w2, g2, b2, m2, v2);
    dim3 gridC(C_ / 32, B_);
    kernelC<<<gridC, 256>>>(x, out);
}

// round 3
// speedup vs baseline: 2.2999x; 2.2999x over previous
#include <cuda_runtime.h>
#include <cuda_bf16.h>
#include <cstdint>
#include <math.h>

// Problem constants
#define B_   128
#define C_   1024
#define R_   256
#define T_   4
#define H_   7
#define W_   7
#define P_   196     // T*H*W
#define EPSV 1e-5f

// ---------------- intermediates (device globals; no allocation allowed) ----
__device__ float g_hmean[B_ * R_];    // mean of hardswish(BN(x·w1^T)) per (b,r)
__device__ float g_coords[B_ * 6];    // sx, sy, st, ex, ey, et per batch

// ---------------- helpers ---------------------------------------------------
__device__ __forceinline__ void mma_tf32(float& d0, float& d1, float& d2, float& d3,
                                         uint32_t a0, uint32_t a1, uint32_t a2, uint32_t a3,
                                         uint32_t b0, uint32_t b1) {
    asm volatile(
        "mma.sync.aligned.m16n8k8.row.col.f32.tf32.tf32.f32 "
        "{%0,%1,%2,%3}, {%4,%5,%6,%7}, {%8,%9}, {%0,%1,%2,%3};\n"
        : "+f"(d0), "+f"(d1), "+f"(d2), "+f"(d3)
        : "r"(a0), "r"(a1), "r"(a2), "r"(a3), "r"(b0), "r"(b1));
}

__device__ __forceinline__ void cp16(float* smem_dst, const float* gsrc, int srcbytes) {
    uint32_t s = (uint32_t)__cvta_generic_to_shared(smem_dst);
    asm volatile("cp.async.ca.shared.global [%0], [%1], 16, %2;\n"
                 :: "r"(s), "l"(gsrc), "r"(srcbytes));
}
__device__ __forceinline__ void cp_commit() {
    asm volatile("cp.async.commit_group;\n");
}
__device__ __forceinline__ void cp_wait0() {
    asm volatile("cp.async.wait_group 0;\n");
}

// ============================================================================
// Kernel A: per-batch GEMM  H[r,p] = sum_c w1[r,c] * x[b,c,p]
// fused BN-affine + hardswish + mean over p  ->  g_hmean[b][r]
//
// One block per batch, 512 threads = 16 warps (8 along M x 2 along N).
// Two N passes of 112 cols (196 real, zero-padded via cp.async zfill).
// K chunked by 32, cp.async double-buffered, tf32 mma m16n8k8.
// Warp tile 32x56 -> 56 accumulators/thread (no spills).
// ============================================================================
#define KC      32
#define AW_S    36     // smem stride of w1 tile
#define XS_S    120    // smem stride of x tile
#define NPW     112    // N columns per pass
#define NKC     32     // K chunks (1024/32)

// smem layout (floats)
#define SM_AW0  0        // 256*36 = 9216
#define SM_AW1  9216
#define SM_XS0  18432    // 32*120 = 3840
#define SM_XS1  22272
#define SM_PART 26112    // 4*256
#define SM_SC   27136
#define SM_BI   27392
#define SM_TOT  27648    // floats -> 110592 bytes

__global__ void __launch_bounds__(512, 1)
kernelA(const float* __restrict__ x, const float* __restrict__ w1,
        const float* __restrict__ g1, const float* __restrict__ b1,
        const float* __restrict__ m1, const float* __restrict__ v1) {
    extern __shared__ float smem[];
    float* AwB[2] = { smem + SM_AW0, smem + SM_AW1 };
    float* XsB[2] = { smem + SM_XS0, smem + SM_XS1 };
    float* part = smem + SM_PART;
    float* sc   = smem + SM_SC;
    float* bi   = smem + SM_BI;

    const int b    = blockIdx.x;
    const int tid  = threadIdx.x;
    const int lane = tid & 31;
    const int warp = tid >> 5;
    const int wm   = warp >> 1;   // 0..7 : M offset wm*32
    const int wn   = warp & 1;    // 0..1 : N offset wn*56

    part[tid]       = 0.f;
    part[tid + 512] = 0.f;
    if (tid < 256) {
        float s = g1[tid] * rsqrtf(v1[tid] + EPSV);
        sc[tid] = s;
        bi[tid] = b1[tid] - m1[tid] * s;
    }

    const float* xb = x + (size_t)b * C_ * P_;

    #pragma unroll 1
    for (int np = 0; np < 2; np++) {
        __syncthreads();   // protect buffers (prev pass / part init visible)

        // ---- prologue: stage chunk 0 ----
        {
            const int kc = 0;
            #pragma unroll
            for (int it = 0; it < 4; it++) {
                int idx = it * 512 + tid;
                int row = idx >> 3, col = (idx & 7) * 4;
                cp16(AwB[0] + row * AW_S + col, w1 + row * C_ + kc + col, 16);
            }
            #pragma unroll
            for (int it = 0; it < 2; it++) {
                int idx = it * 512 + tid;
                if (idx < 896) {
                    int row = idx / 28, colg = idx - row * 28;
                    int col = colg * 4;
                    int p = np * NPW + col;
                    int sb = (p < P_) ? 16 : 0;
                    const float* src = xb + (size_t)(kc + row) * P_ + (p < P_ ? p : 0);
                    cp16(XsB[0] + row * XS_S + col, src, sb);
                }
            }
            cp_commit();
        }

        float d[2][7][4];
        #pragma unroll
        for (int mt = 0; mt < 2; mt++)
            #pragma unroll
            for (int nt = 0; nt < 7; nt++)
                #pragma unroll
                for (int j = 0; j < 4; j++) d[mt][nt][j] = 0.f;

        #pragma unroll 1
        for (int kci = 0; kci < NKC; kci++) {
            cp_wait0();
            __syncthreads();

            if (kci + 1 < NKC) {
                const int kc = (kci + 1) * KC;
                float* Awn = AwB[(kci + 1) & 1];
                float* Xsn = XsB[(kci + 1) & 1];
                #pragma unroll
                for (int it = 0; it < 4; it++) {
                    int idx = it * 512 + tid;
                    int row = idx >> 3, col = (idx & 7) * 4;
                    cp16(Awn + row * AW_S + col, w1 + row * C_ + kc + col, 16);
                }
                #pragma unroll
                for (int it = 0; it < 2; it++) {
                    int idx = it * 512 + tid;
                    if (idx < 896) {
                        int row = idx / 28, colg = idx - row * 28;
                        int col = colg * 4;
                        int p = np * NPW + col;
                        int sb = (p < P_) ? 16 : 0;
                        const float* src = xb + (size_t)(kc + row) * P_ + (p < P_ ? p : 0);
                        cp16(Xsn + row * XS_S + col, src, sb);
                    }
                }
                cp_commit();
            }

            const float* Aw = AwB[kci & 1];
            const float* Xs = XsB[kci & 1];

            #pragma unroll
            for (int kk = 0; kk < 4; kk++) {
                uint32_t a[2][4];
                const int ar = wm * 32 + (lane >> 2);
                const int ac = kk * 8 + (lane & 3);
                #pragma unroll
                for (int mt = 0; mt < 2; mt++) {
                    a[mt][0] = __float_as_uint(Aw[(ar + mt * 16    ) * AW_S + ac    ]);
                    a[mt][1] = __float_as_uint(Aw[(ar + mt * 16 + 8) * AW_S + ac    ]);
                    a[mt][2] = __float_as_uint(Aw[(ar + mt * 16    ) * AW_S + ac + 4]);
                    a[mt][3] = __float_as_uint(Aw[(ar + mt * 16 + 8) * AW_S + ac + 4]);
                }
                uint32_t bb[7][2];
                const int br = kk * 8 + (lane & 3);
                const int bc = wn * 56 + (lane >> 2);
                #pragma unroll
                for (int nt = 0; nt < 7; nt++) {
                    bb[nt][0] = __float_as_uint(Xs[ br      * XS_S + bc + nt * 8]);
                    bb[nt][1] = __float_as_uint(Xs[(br + 4) * XS_S + bc + nt * 8]);
                }
                #pragma unroll
                for (int mt = 0; mt < 2; mt++)
                    #pragma unroll
                    for (int nt = 0; nt < 7; nt++)
                        mma_tf32(d[mt][nt][0], d[mt][nt][1], d[mt][nt][2], d[mt][nt][3],
                                 a[mt][0], a[mt][1], a[mt][2], a[mt][3],
                                 bb[nt][0], bb[nt][1]);
            }
        }

        // epilogue: BN affine + hardswish + per-row partial sums
        const int pbase = np * NPW + wn * 56 + (lane & 3) * 2;
        #pragma unroll
        for (int mt = 0; mt < 2; mt++) {
            const int r0 = wm * 32 + mt * 16 + (lane >> 2);
            const int r1 = r0 + 8;
            const float s0c = sc[r0], b0c = bi[r0];
            const float s1c = sc[r1], b1c = bi[r1];
            float acc0 = 0.f, acc1 = 0.f;
            #pragma unroll
            for (int nt = 0; nt < 7; nt++) {
                #pragma unroll
                for (int jj = 0; jj < 2; jj++) {
                    int p = pbase + nt * 8 + jj;
                    if (p < P_) {
                        float h0 = d[mt][nt][jj] * s0c + b0c;
                        acc0 += h0 * fminf(fmaxf(h0 + 3.f, 0.f), 6.f) * (1.f / 6.f);
                        float h1 = d[mt][nt][2 + jj] * s1c + b1c;
                        acc1 += h1 * fminf(fmaxf(h1 + 3.f, 0.f), 6.f) * (1.f / 6.f);
                    }
                }
            }
            acc0 += __shfl_xor_sync(0xFFFFFFFFu, acc0, 1);
            acc0 += __shfl_xor_sync(0xFFFFFFFFu, acc0, 2);
            acc1 += __shfl_xor_sync(0xFFFFFFFFu, acc1, 1);
            acc1 += __shfl_xor_sync(0xFFFFFFFFu, acc1, 2);
            if ((lane & 3) == 0) {
                // exclusive writer per (np, wn, r)
                part[(np * 2 + wn) * 256 + r0] += acc0;
                part[(np * 2 + wn) * 256 + r1] += acc1;
            }
        }
    }

    __syncthreads();
    if (tid < 256)
        g_hmean[b * R_ + tid] = (part[tid] + part[256 + tid] +
                                 part[512 + tid] + part[768 + tid]) * (1.f / (float)P_);
}

// ============================================================================
// Kernel B: logits = hmean @ w2^T ; BN2 ; sigmoid ; ROI coords
// ============================================================================
__global__ void kernelB(const float* __restrict__ w2, const float* __restrict__ g2,
                        const float* __restrict__ b2, const float* __restrict__ m2,
                        const float* __restrict__ v2) {
    const int b = blockIdx.x;
    const int lane = threadIdx.x;
    const float* h = g_hmean + b * R_;

    float lg[6];
    #pragma unroll
    for (int j = 0; j < 6; j++) {
        float s = 0.f;
        #pragma unroll
        for (int r = lane; r < R_; r += 32) s += h[r] * w2[j * R_ + r];
        #pragma unroll
        for (int off = 16; off; off >>= 1) s += __shfl_xor_sync(0xFFFFFFFFu, s, off);
        lg[j] = s;
    }
    if (lane < 6) {
        const int j = lane;
        float sf = g2[j] * rsqrtf(v2[j] + EPSV);
        float l  = (lg[j] - m2[j]) * sf + b2[j];
        float sig = 1.f / (1.f + expf(-l));
        const float SC[3] = {7.f, 7.f, 4.f};
        float outv = (j < 3) ? (0.5f * sig * SC[j])
                             : ((1.f - 0.5f * sig) * SC[j - 3]);
        g_coords[b * 6 + j] = outv;
    }
}

// ============================================================================
// Kernel C: ROI align 3D. Block = (32-channel tile, batch). 256 threads.
// ============================================================================
__global__ void __launch_bounds__(256)
kernelC(const float* __restrict__ x, float* __restrict__ out) {
    __shared__ float xs[32 * 200];
    __shared__ int   ilo[13], ihi[13];
    __shared__ float ww0[13], ww1[13];

    const int tid = threadIdx.x;
    const int b   = blockIdx.y;
    const int cc  = blockIdx.x * 32;

    const float* xb = x + ((size_t)b * C_ + cc) * P_;

    for (int i = tid; i < 32 * 49; i += 256) {
        int c = i / 49, q = i - c * 49;
        float4 v = reinterpret_cast<const float4*>(xb + (size_t)c * P_)[q];
        float* dst = xs + c * 200 + q * 4;
        dst[0] = v.x; dst[1] = v.y; dst[2] = v.z; dst[3] = v.w;
    }

    if (tid < 13) {
        int axis = (tid < 5) ? 0 : ((tid < 10) ? 1 : 2);
        int i    = (tid < 5) ? tid : ((tid < 10) ? tid - 5 : tid - 10);
        int   n    = (axis == 2) ? 3 : 5;
        float size = (axis == 2) ? 4.f : 7.f;
        float s = g_coords[b * 6 + axis];
        float e = g_coords[b * 6 + 3 + axis];
        float bin = (e - s) / (float)n;
        float c = s + ((float)i + 0.5f) * bin;
        float valid = (c >= -1.f && c <= size) ? 1.f : 0.f;
        c = fminf(fmaxf(c, 0.f), size - 1.f);
        int lo = (int)floorf(c);
        int hi = min(lo + 1, (int)size - 1);
        float f = c - (float)lo;
        ilo[tid] = lo; ihi[tid] = hi;
        ww0[tid] = (1.f - f) * valid;
        ww1[tid] = f * valid;
    }
    __syncthreads();

    for (int o = tid; o < 32 * 75; o += 256) {
        int c = o / 75, p = o - c * 75;
        int ot = p / 25, r = p - ot * 25;
        int oy = r / 5,  ox = r - oy * 5;

        int t0 = ilo[10 + ot], t1 = ihi[10 + ot];
        float tw0 = ww0[10 + ot], tw1 = ww1[10 + ot];
        int y0 = ilo[5 + oy], y1 = ihi[5 + oy];
        float yw0 = ww0[5 + oy], yw1 = ww1[5 + oy];
        int x0 = ilo[ox], x1 = ihi[ox];
        float xw0 = ww0[ox], xw1 = ww1[ox];

        const float* base = xs + c * 200;
        float v00 = xw0 * base[t0 * 49 + y0 * 7 + x0] + xw1 * base[t0 * 49 + y0 * 7 + x1];
        float v01 = xw0 * base[t0 * 49 + y1 * 7 + x0] + xw1 * base[t0 * 49 + y1 * 7 + x1];
        float v10 = xw0 * base[t1 * 49 + y0 * 7 + x0] + xw1 * base[t1 * 49 + y0 * 7 + x1];
        float v11 = xw0 * base[t1 * 49 + y1 * 7 + x0] + xw1 * base[t1 * 49 + y1 * 7 + x1];
        float v = tw0 * (yw0 * v00 + yw1 * v01) + tw1 * (yw0 * v10 + yw1 * v11);

        out[((size_t)(b * C_ + cc + c)) * 75 + p] = v;
    }
}

// ============================================================================
extern "C" void kernel_launch(void* const* d_in, const int* in_sizes, int n_in,
                              void* d_out, int out_size) {
    const float* x  = (const float*)d_in[0];
    const float* w1 = (const float*)d_in[1];
    const float* g1 = (const float*)d_in[2];
    const float* b1 = (const float*)d_in[3];
    const float* m1 = (const float*)d_in[4];
    const float* v1 = (const float*)d_in[5];
    const float* w2 = (const float*)d_in[6];
    const float* g2 = (const float*)d_in[7];
    const float* b2 = (const float*)d_in[8];
    const float* m2 = (const float*)d_in[9];
    const float* v2 = (const float*)d_in[10];
    float* out = (float*)d_out;

    const size_t smemA = SM_TOT * sizeof(float);  // 110592 B
    cudaFuncSetAttribute(kernelA, cudaFuncAttributeMaxDynamicSharedMemorySize, (int)smemA);

    kernelA<<<B_, 512, smemA>>>(x, w1, g1, b1, m1, v1);
    kernelB<<<B_, 32>>>(w2, g2, b2, m2, v2);
    dim3 gridC(C_ / 32, B_);
    kernelC<<<gridC, 256>>>(x, out);
}

// round 5
// speedup vs baseline: 2.6684x; 1.1602x over previous
#include <cuda_runtime.h>
#include <cuda_bf16.h>
#include <cstdint>
#include <math.h>

// Problem constants
#define B_   128
#define C_   1024
#define R_   256
#define T_   4
#define H_   7
#define W_   7
#define P_   196     // T*H*W
#define EPSV 1e-5f

// ---------------- intermediates (device globals; no allocation allowed) ----
__device__ float g_hmean[B_ * R_];    // mean of hardswish(BN(x·w1^T)) per (b,r)
__device__ float g_coords[B_ * 6];    // sx, sy, st, ex, ey, et per batch

// ---------------- helpers ---------------------------------------------------
__device__ __forceinline__ void mma_tf32(float& d0, float& d1, float& d2, float& d3,
                                         uint32_t a0, uint32_t a1, uint32_t a2, uint32_t a3,
                                         uint32_t b0, uint32_t b1) {
    asm volatile(
        "mma.sync.aligned.m16n8k8.row.col.f32.tf32.tf32.f32 "
        "{%0,%1,%2,%3}, {%4,%5,%6,%7}, {%8,%9}, {%0,%1,%2,%3};\n"
        : "+f"(d0), "+f"(d1), "+f"(d2), "+f"(d3)
        : "r"(a0), "r"(a1), "r"(a2), "r"(a3), "r"(b0), "r"(b1));
}

__device__ __forceinline__ void cp16(float* smem_dst, const float* gsrc, int srcbytes) {
    uint32_t s = (uint32_t)__cvta_generic_to_shared(smem_dst);
    asm volatile("cp.async.ca.shared.global [%0], [%1], 16, %2;\n"
                 :: "r"(s), "l"(gsrc), "r"(srcbytes));
}
__device__ __forceinline__ void cp_commit() { asm volatile("cp.async.commit_group;\n"); }
__device__ __forceinline__ void cp_wait0()  { asm volatile("cp.async.wait_group 0;\n"); }
__device__ __forceinline__ void cp_wait1()  { asm volatile("cp.async.wait_group 1;\n"); }

// ============================================================================
// Kernel A: GEMM  H[r,p] = sum_c w1[r,c] * x[b,c,p]
// fused BN-affine + hardswish + mean over p  ->  g_hmean[b][r]
//
// CTA = (mhalf, batch): 128 rows of r, all 196 cols (two passes of 112).
// 256 threads = 8 warps (4 along M x 2 along N), warp tile 32x56.
// K chunked by 32, cp.async 3-stage pipeline, tf32 mma m16n8k8.
// 2 CTAs resident per SM (regs<=128, smem ~102KB).
// ============================================================================
#define KC      32
#define NKC     32     // 1024/32
#define AW_S    36     // smem stride of w1 tile
#define XS_S    120    // smem stride of x tile
#define NPW     112    // N columns per pass

// smem layout (floats)
#define SM_AW   0        // 3 stages x 128*36 = 3*4608
#define SM_XS   13824    // 3 stages x 32*120 = 3*3840
#define SM_PART 25344    // 4*128
#define SM_SC   25856    // 128
#define SM_BI   25984    // 128
#define SM_TOT  26112    // floats -> 104448 bytes

__global__ void __launch_bounds__(256, 2)
kernelA(const float* __restrict__ x, const float* __restrict__ w1,
        const float* __restrict__ g1, const float* __restrict__ b1,
        const float* __restrict__ m1, const float* __restrict__ v1) {
    extern __shared__ float smem[];
    float* AwB[3] = { smem + SM_AW, smem + SM_AW + 4608, smem + SM_AW + 9216 };
    float* XsB[3] = { smem + SM_XS, smem + SM_XS + 3840, smem + SM_XS + 7680 };
    float* part = smem + SM_PART;
    float* sc   = smem + SM_SC;
    float* bi   = smem + SM_BI;

    const int mh   = blockIdx.x;   // 0/1 : which 128-row half of r
    const int b    = blockIdx.y;
    const int tid  = threadIdx.x;
    const int lane = tid & 31;
    const int warp = tid >> 5;
    const int wm   = warp >> 1;    // 0..3 : M offset wm*32 (within 128-row half)
    const int wn   = warp & 1;     // 0..1 : N offset wn*56
    const int rbase = mh * 128;    // global r offset of this CTA

    part[tid]       = 0.f;
    part[tid + 256] = 0.f;
    if (tid < 128) {
        int r = rbase + tid;
        float s = g1[r] * rsqrtf(v1[r] + EPSV);
        sc[tid] = s;
        bi[tid] = b1[r] - m1[r] * s;
    }

    const float* xb = x + (size_t)b * C_ * P_;

    #pragma unroll 1
    for (int np = 0; np < 2; np++) {
        __syncthreads();   // protect buffers (prev pass reads / part init visible)

        // ---- staging helpers ----
        auto stageA = [&](float* Aw, int kc) {
            #pragma unroll
            for (int it = 0; it < 4; it++) {        // 1024 cp16
                int idx = it * 256 + tid;
                int row = idx >> 3, c4 = idx & 7;   // row 0..127, 16B chunk 0..7
                cp16(Aw + row * AW_S + c4 * 4,
                     w1 + (size_t)(rbase + row) * C_ + kc + c4 * 4, 16);
            }
        };
        auto stageB = [&](float* Xs, int kc) {
            #pragma unroll
            for (int it = 0; it < 4; it++) {        // 896 cp16
                int idx = it * 256 + tid;
                if (idx < 896) {
                    int row = idx / 28, colg = idx - row * 28;
                    int col = colg * 4;
                    int p = np * NPW + col;
                    int sb = (p < P_) ? 16 : 0;
                    const float* src = xb + (size_t)(kc + row) * P_ + (p < P_ ? p : 0);
                    cp16(Xs + row * XS_S + col, src, sb);
                }
            }
        };

        // ---- prologue: stage chunks 0 and 1 ----
        stageA(AwB[0], 0);  stageB(XsB[0], 0);  cp_commit();
        stageA(AwB[1], KC); stageB(XsB[1], KC); cp_commit();

        float d[2][7][4];
        #pragma unroll
        for (int mt = 0; mt < 2; mt++)
            #pragma unroll
            for (int nt = 0; nt < 7; nt++)
                #pragma unroll
                for (int j = 0; j < 4; j++) d[mt][nt][j] = 0.f;

        #pragma unroll 1
        for (int kci = 0; kci < NKC; kci++) {
            if (kci < NKC - 1) cp_wait1(); else cp_wait0();
            __syncthreads();

            if (kci + 2 < NKC) {
                int nb = (kci + 2) % 3;
                stageA(AwB[nb], (kci + 2) * KC);
                stageB(XsB[nb], (kci + 2) * KC);
                cp_commit();
            }

            const float* Aw = AwB[kci % 3];
            const float* Xs = XsB[kci % 3];

            #pragma unroll
            for (int kk = 0; kk < 4; kk++) {
                uint32_t a[2][4];
                const int ar = wm * 32 + (lane >> 2);
                const int ac = kk * 8 + (lane & 3);
                #pragma unroll
                for (int mt = 0; mt < 2; mt++) {
                    a[mt][0] = __float_as_uint(Aw[(ar + mt * 16    ) * AW_S + ac    ]);
                    a[mt][1] = __float_as_uint(Aw[(ar + mt * 16 + 8) * AW_S + ac    ]);
                    a[mt][2] = __float_as_uint(Aw[(ar + mt * 16    ) * AW_S + ac + 4]);
                    a[mt][3] = __float_as_uint(Aw[(ar + mt * 16 + 8) * AW_S + ac + 4]);
                }
                uint32_t bb[7][2];
                const int br = kk * 8 + (lane & 3);
                const int bc = wn * 56 + (lane >> 2);
                #pragma unroll
                for (int nt = 0; nt < 7; nt++) {
                    bb[nt][0] = __float_as_uint(Xs[ br      * XS_S + bc + nt * 8]);
                    bb[nt][1] = __float_as_uint(Xs[(br + 4) * XS_S + bc + nt * 8]);
                }
                #pragma unroll
                for (int mt = 0; mt < 2; mt++)
                    #pragma unroll
                    for (int nt = 0; nt < 7; nt++)
                        mma_tf32(d[mt][nt][0], d[mt][nt][1], d[mt][nt][2], d[mt][nt][3],
                                 a[mt][0], a[mt][1], a[mt][2], a[mt][3],
                                 bb[nt][0], bb[nt][1]);
            }
        }

        // epilogue: BN affine + hardswish + per-row partial sums (local 128 rows)
        const int pbase = np * NPW + wn * 56 + (lane & 3) * 2;
        #pragma unroll
        for (int mt = 0; mt < 2; mt++) {
            const int rl0 = wm * 32 + mt * 16 + (lane >> 2);
            const int rl1 = rl0 + 8;
            const float s0c = sc[rl0], b0c = bi[rl0];
            const float s1c = sc[rl1], b1c = bi[rl1];
            float acc0 = 0.f, acc1 = 0.f;
            #pragma unroll
            for (int nt = 0; nt < 7; nt++) {
                #pragma unroll
                for (int jj = 0; jj < 2; jj++) {
                    int p = pbase + nt * 8 + jj;
                    if (p < P_) {
                        float h0 = d[mt][nt][jj] * s0c + b0c;
                        acc0 += h0 * fminf(fmaxf(h0 + 3.f, 0.f), 6.f) * (1.f / 6.f);
                        float h1 = d[mt][nt][2 + jj] * s1c + b1c;
                        acc1 += h1 * fminf(fmaxf(h1 + 3.f, 0.f), 6.f) * (1.f / 6.f);
                    }
                }
            }
            acc0 += __shfl_xor_sync(0xFFFFFFFFu, acc0, 1);
            acc0 += __shfl_xor_sync(0xFFFFFFFFu, acc0, 2);
            acc1 += __shfl_xor_sync(0xFFFFFFFFu, acc1, 1);
            acc1 += __shfl_xor_sync(0xFFFFFFFFu, acc1, 2);
            if ((lane & 3) == 0) {
                // exclusive writer per (np, wn, rl)
                part[(np * 2 + wn) * 128 + rl0] += acc0;
                part[(np * 2 + wn) * 128 + rl1] += acc1;
            }
        }
    }

    __syncthreads();
    if (tid < 128)
        g_hmean[b * R_ + rbase + tid] = (part[tid] + part[128 + tid] +
                                         part[256 + tid] + part[384 + tid]) * (1.f / (float)P_);
}

// ============================================================================
// Kernel B: logits = hmean @ w2^T ; BN2 ; sigmoid ; ROI coords
// ============================================================================
__global__ void kernelB(const float* __restrict__ w2, const float* __restrict__ g2,
                        const float* __restrict__ b2, const float* __restrict__ m2,
                        const float* __restrict__ v2) {
    const int b = blockIdx.x;
    const int lane = threadIdx.x;
    const float* h = g_hmean + b * R_;

    float lg[6];
    #pragma unroll
    for (int j = 0; j < 6; j++) {
        float s = 0.f;
        #pragma unroll
        for (int r = lane; r < R_; r += 32) s += h[r] * w2[j * R_ + r];
        #pragma unroll
        for (int off = 16; off; off >>= 1) s += __shfl_xor_sync(0xFFFFFFFFu, s, off);
        lg[j] = s;
    }
    if (lane < 6) {
        const int j = lane;
        float sf = g2[j] * rsqrtf(v2[j] + EPSV);
        float l  = (lg[j] - m2[j]) * sf + b2[j];
        float sig = 1.f / (1.f + expf(-l));
        const float SC[3] = {7.f, 7.f, 4.f};
        float outv = (j < 3) ? (0.5f * sig * SC[j])
                             : ((1.f - 0.5f * sig) * SC[j - 3]);
        g_coords[b * 6 + j] = outv;
    }
}

// ============================================================================
// Kernel C: ROI align 3D. Block = (32-channel tile, batch). 256 threads.
// ============================================================================
__global__ void __launch_bounds__(256)
kernelC(const float* __restrict__ x, float* __restrict__ out) {
    __shared__ float xs[32 * 200];
    __shared__ int   ilo[13], ihi[13];
    __shared__ float ww0[13], ww1[13];

    const int tid = threadIdx.x;
    const int b   = blockIdx.y;
    const int cc  = blockIdx.x * 32;

    const float* xb = x + ((size_t)b * C_ + cc) * P_;

    for (int i = tid; i < 32 * 49; i += 256) {
        int c = i / 49, q = i - c * 49;
        float4 v = reinterpret_cast<const float4*>(xb + (size_t)c * P_)[q];
        float* dst = xs + c * 200 + q * 4;
        dst[0] = v.x; dst[1] = v.y; dst[2] = v.z; dst[3] = v.w;
    }

    if (tid < 13) {
        int axis = (tid < 5) ? 0 : ((tid < 10) ? 1 : 2);
        int i    = (tid < 5) ? tid : ((tid < 10) ? tid - 5 : tid - 10);
        int   n    = (axis == 2) ? 3 : 5;
        float size = (axis == 2) ? 4.f : 7.f;
        float s = g_coords[b * 6 + axis];
        float e = g_coords[b * 6 + 3 + axis];
        float bin = (e - s) / (float)n;
        float c = s + ((float)i + 0.5f) * bin;
        float valid = (c >= -1.f && c <= size) ? 1.f : 0.f;
        c = fminf(fmaxf(c, 0.f), size - 1.f);
        int lo = (int)floorf(c);
        int hi = min(lo + 1, (int)size - 1);
        float f = c - (float)lo;
        ilo[tid] = lo; ihi[tid] = hi;
        ww0[tid] = (1.f - f) * valid;
        ww1[tid] = f * valid;
    }
    __syncthreads();

    for (int o = tid; o < 32 * 75; o += 256) {
        int c = o / 75, p = o - c * 75;
        int ot = p / 25, r = p - ot * 25;
        int oy = r / 5,  ox = r - oy * 5;

        int t0 = ilo[10 + ot], t1 = ihi[10 + ot];
        float tw0 = ww0[10 + ot], tw1 = ww1[10 + ot];
        int y0 = ilo[5 + oy], y1 = ihi[5 + oy];
        float yw0 = ww0[5 + oy], yw1 = ww1[5 + oy];
        int x0 = ilo[ox], x1 = ihi[ox];
        float xw0 = ww0[ox], xw1 = ww1[ox];

        const float* base = xs + c * 200;
        float v00 = xw0 * base[t0 * 49 + y0 * 7 + x0] + xw1 * base[t0 * 49 + y0 * 7 + x1];
        float v01 = xw0 * base[t0 * 49 + y1 * 7 + x0] + xw1 * base[t0 * 49 + y1 * 7 + x1];
        float v10 = xw0 * base[t1 * 49 + y0 * 7 + x0] + xw1 * base[t1 * 49 + y0 * 7 + x1];
        float v11 = xw0 * base[t1 * 49 + y1 * 7 + x0] + xw1 * base[t1 * 49 + y1 * 7 + x1];
        float v = tw0 * (yw0 * v00 + yw1 * v01) + tw1 * (yw0 * v10 + yw1 * v11);

        out[((size_t)(b * C_ + cc + c)) * 75 + p] = v;
    }
}

// ============================================================================
extern "C" void kernel_launch(void* const* d_in, const int* in_sizes, int n_in,
                              void* d_out, int out_size) {
    const float* x  = (const float*)d_in[0];
    const float* w1 = (const float*)d_in[1];
    const float* g1 = (const float*)d_in[2];
    const float* b1 = (const float*)d_in[3];
    const float* m1 = (const float*)d_in[4];
    const float* v1 = (const float*)d_in[5];
    const float* w2 = (const float*)d_in[6];
    const float* g2 = (const float*)d_in[7];
    const float* b2 = (const float*)d_in[8];
    const float* m2 = (const float*)d_in[9];
    const float* v2 = (const float*)d_in[10];
    float* out = (float*)d_out;

    const size_t smemA = SM_TOT * sizeof(float);  // 104448 B
    cudaFuncSetAttribute(kernelA, cudaFuncAttributeMaxDynamicSharedMemorySize, (int)smemA);

    dim3 gridA(2, B_);
    kernelA<<<gridA, 256, smemA>>>(x, w1, g1, b1, m1, v1);
    kernelB<<<B_, 32>>>(w2, g2, b2, m2, v2);
    dim3 gridC(C_ / 32, B_);
    kernelC<<<gridC, 256>>>(x, out);
}

// round 6
// speedup vs baseline: 3.1935x; 1.1968x over previous
#include <cuda_runtime.h>
#include <cuda_fp16.h>
#include <cstdint>
#include <math.h>

// Problem constants
#define B_   128
#define C_   1024
#define R_   256
#define T_   4
#define H_   7
#define W_   7
#define P_   196     // T*H*W
#define EPSV 1e-5f

// ---------------- intermediates (device globals; no allocation allowed) ----
__device__ float  g_hmean[B_ * R_];
__device__ float  g_coords[B_ * 6];
__device__ __half g_xh[(size_t)B_ * P_ * C_];   // x transposed: [b][p][c] fp16
__device__ __half g_w1h[R_ * C_];               // w1 fp16: [r][c]

// ---------------- helpers ---------------------------------------------------
__device__ __forceinline__ void mma_f16(float& d0, float& d1, float& d2, float& d3,
                                        uint32_t a0, uint32_t a1, uint32_t a2, uint32_t a3,
                                        uint32_t b0, uint32_t b1) {
    asm volatile(
        "mma.sync.aligned.m16n8k16.row.col.f32.f16.f16.f32 "
        "{%0,%1,%2,%3}, {%4,%5,%6,%7}, {%8,%9}, {%0,%1,%2,%3};\n"
        : "+f"(d0), "+f"(d1), "+f"(d2), "+f"(d3)
        : "r"(a0), "r"(a1), "r"(a2), "r"(a3), "r"(b0), "r"(b1));
}

__device__ __forceinline__ void cp16(void* smem_dst, const void* gsrc, int srcbytes) {
    uint32_t s = (uint32_t)__cvta_generic_to_shared(smem_dst);
    asm volatile("cp.async.ca.shared.global [%0], [%1], 16, %2;\n"
                 :: "r"(s), "l"(gsrc), "r"(srcbytes));
}
__device__ __forceinline__ void cp_commit() { asm volatile("cp.async.commit_group;\n"); }
__device__ __forceinline__ void cp_wait0()  { asm volatile("cp.async.wait_group 0;\n"); }
__device__ __forceinline__ void cp_wait1()  { asm volatile("cp.async.wait_group 1;\n"); }

// ============================================================================
// Kernel P: blockIdx.x < 16 : transpose+convert x[b][c][p] f32 -> g_xh[b][p][c] fp16
//           blockIdx.x ==16 : convert w1 -> g_w1h (2 rows per blockIdx.y)
// ============================================================================
__global__ void __launch_bounds__(256)
kernelP(const float* __restrict__ x, const float* __restrict__ w1) {
    const int tid = threadIdx.x;
    const int b   = blockIdx.y;

    if (blockIdx.x == 16) {   // w1 convert: rows [2b, 2b+2)
        const int e0 = b * 2048;                 // element base
        #pragma unroll
        for (int it = 0; it < 2; it++) {
            int idx = it * 256 + tid;            // float4 index within 512
            float4 v = reinterpret_cast<const float4*>(w1 + e0)[idx];
            __half2 h0 = __floats2half2_rn(v.x, v.y);
            __half2 h1 = __floats2half2_rn(v.z, v.w);
            uint2 u;
            u.x = *reinterpret_cast<uint32_t*>(&h0);
            u.y = *reinterpret_cast<uint32_t*>(&h1);
            reinterpret_cast<uint2*>(g_w1h + e0)[idx] = u;
        }
        return;
    }

    // transpose tile: c in [c0, c0+64), all p
    __shared__ unsigned short xs[64 * 202];
    const int c0 = blockIdx.x * 64;

    for (int idx = tid; idx < 64 * 49; idx += 256) {
        int c = idx / 49, q = idx - c * 49;
        float4 v = reinterpret_cast<const float4*>(
                       x + ((size_t)b * C_ + c0 + c) * P_)[q];
        unsigned short* dst = xs + c * 202 + q * 4;
        dst[0] = __half_as_ushort(__float2half_rn(v.x));
        dst[1] = __half_as_ushort(__float2half_rn(v.y));
        dst[2] = __half_as_ushort(__float2half_rn(v.z));
        dst[3] = __half_as_ushort(__float2half_rn(v.w));
    }
    __syncthreads();

    // write x_h[b][p][c0..c0+63]: uint per thread = 2 consecutive c
    uint32_t* outu = reinterpret_cast<uint32_t*>(g_xh);
    for (int idx = tid; idx < P_ * 32; idx += 256) {
        int p = idx >> 5, ch = idx & 31;                 // ch = c-pair
        uint32_t lo = xs[(2 * ch    ) * 202 + p];
        uint32_t hi = xs[(2 * ch + 1) * 202 + p];
        outu[((size_t)b * P_ + p) * (C_ / 2) + (c0 >> 1) + ch] = lo | (hi << 16);
    }
}

// ============================================================================
// Kernel A: GEMM  H[r,p] = sum_c w1[r,c] * x[b,c,p]   (fp16 HMMA m16n8k16)
// fused BN-affine + hardswish + mean over p  ->  g_hmean[b][r]
// CTA = (mhalf, batch): 128 r rows x 196 p (two passes of 112).
// 256 threads = 8 warps (4M x 2N), warp tile 32x56. 3-stage cp.async.
// A = g_w1h [r][c] (K-major), B = g_xh [p][c] (K-major => mma col B).
// ============================================================================
#define KC      32
#define NKC     32     // 1024/32
#define NPW     112    // N (p) columns per pass
#define SA_H    40     // A smem stride in fp16 (80 B)
#define SB_H    72     // B smem stride in fp16 (144 B)
#define ASZ     10240  // 128*80
#define BSZ     16128  // 112*144

// smem byte offsets
#define OFF_A    0
#define OFF_B    (3 * ASZ)                   // 30720
#define OFF_PART (OFF_B + 3 * BSZ)           // 79104 (512 f32)
#define OFF_SC   (OFF_PART + 2048)           // 81152 (128 f32)
#define OFF_BI   (OFF_SC + 512)              // 81664 (128 f32)
#define SMEM_A_TOTAL (OFF_BI + 512)          // 82176 B

__global__ void __launch_bounds__(256, 2)
kernelA(const float* __restrict__ g1, const float* __restrict__ b1,
        const float* __restrict__ m1, const float* __restrict__ v1) {
    extern __shared__ __align__(16) char smem[];
    float* part = reinterpret_cast<float*>(smem + OFF_PART);
    float* sc   = reinterpret_cast<float*>(smem + OFF_SC);
    float* bi   = reinterpret_cast<float*>(smem + OFF_BI);

    const int mh   = blockIdx.x;   // 0/1 : 128-row half of r
    const int b    = blockIdx.y;
    const int tid  = threadIdx.x;
    const int lane = tid & 31;
    const int warp = tid >> 5;
    const int wm   = warp >> 1;    // 0..3 : M offset wm*32
    const int wn   = warp & 1;     // 0..1 : N offset wn*56
    const int rbase = mh * 128;

    part[tid]       = 0.f;
    part[tid + 256] = 0.f;
    if (tid < 128) {
        int r = rbase + tid;
        float s = g1[r] * rsqrtf(v1[r] + EPSV);
        sc[tid] = s;
        bi[tid] = b1[r] - m1[r] * s;
    }

    const __half* w1h = g_w1h;
    const __half* xh  = g_xh + (size_t)b * P_ * C_;

    #pragma unroll 1
    for (int np = 0; np < 2; np++) {
        __syncthreads();   // prev-pass reads done / part init visible

        auto stageA = [&](int s, int kc) {
            char* base = smem + OFF_A + s * ASZ;
            #pragma unroll
            for (int it = 0; it < 2; it++) {       // 512 cp16
                int idx = it * 256 + tid;
                int row = idx >> 2, ch = idx & 3;  // row 0..127, 16B chunk
                cp16(base + row * 80 + ch * 16,
                     w1h + (size_t)(rbase + row) * C_ + kc + ch * 8, 16);
            }
        };
        auto stageB = [&](int s, int kc) {
            char* base = smem + OFF_B + s * BSZ;
            #pragma unroll
            for (int it = 0; it < 2; it++) {       // 448 cp16
                int idx = it * 256 + tid;
                if (idx < 448) {
                    int row = idx >> 2, ch = idx & 3;   // p-local 0..111
                    int p = np * NPW + row;
                    int ok = (p < P_);
                    const __half* src = xh + (size_t)(ok ? p : 0) * C_ + kc + ch * 8;
                    cp16(base + row * 144 + ch * 16, src, ok ? 16 : 0);
                }
            }
        };

        stageA(0, 0);  stageB(0, 0);  cp_commit();
        stageA(1, KC); stageB(1, KC); cp_commit();

        float d[2][7][4];
        #pragma unroll
        for (int mt = 0; mt < 2; mt++)
            #pragma unroll
            for (int nt = 0; nt < 7; nt++)
                #pragma unroll
                for (int j = 0; j < 4; j++) d[mt][nt][j] = 0.f;

        #pragma unroll 1
        for (int kci = 0; kci < NKC; kci++) {
            if (kci < NKC - 1) cp_wait1(); else cp_wait0();
            __syncthreads();

            if (kci + 2 < NKC) {
                int nb = (kci + 2) % 3;
                stageA(nb, (kci + 2) * KC);
                stageB(nb, (kci + 2) * KC);
                cp_commit();
            }

            const __half* Aw = reinterpret_cast<const __half*>(smem + OFF_A + (kci % 3) * ASZ);
            const __half* Xs = reinterpret_cast<const __half*>(smem + OFF_B + (kci % 3) * BSZ);

            #pragma unroll
            for (int kk = 0; kk < 2; kk++) {
                const int acol = kk * 16 + (lane & 3) * 2;
                uint32_t a[2][4];
                const int ar = wm * 32 + (lane >> 2);
                #pragma unroll
                for (int mt = 0; mt < 2; mt++) {
                    const __half* p0 = Aw + (ar + mt * 16) * SA_H + acol;
                    const __half* p1 = Aw + (ar + mt * 16 + 8) * SA_H + acol;
                    a[mt][0] = *reinterpret_cast<const uint32_t*>(p0);
                    a[mt][1] = *reinterpret_cast<const uint32_t*>(p1);
                    a[mt][2] = *reinterpret_cast<const uint32_t*>(p0 + 8);
                    a[mt][3] = *reinterpret_cast<const uint32_t*>(p1 + 8);
                }
                uint32_t bb[7][2];
                const int bn = wn * 56 + (lane >> 2);
                #pragma unroll
                for (int nt = 0; nt < 7; nt++) {
                    const __half* pb = Xs + (bn + nt * 8) * SB_H + acol;
                    bb[nt][0] = *reinterpret_cast<const uint32_t*>(pb);
                    bb[nt][1] = *reinterpret_cast<const uint32_t*>(pb + 8);
                }
                #pragma unroll
                for (int mt = 0; mt < 2; mt++)
                    #pragma unroll
                    for (int nt = 0; nt < 7; nt++)
                        mma_f16(d[mt][nt][0], d[mt][nt][1], d[mt][nt][2], d[mt][nt][3],
                                a[mt][0], a[mt][1], a[mt][2], a[mt][3],
                                bb[nt][0], bb[nt][1]);
            }
        }

        // epilogue: BN affine + hardswish + per-row partial sums
        const int pbase = np * NPW + wn * 56 + (lane & 3) * 2;
        #pragma unroll
        for (int mt = 0; mt < 2; mt++) {
            const int rl0 = wm * 32 + mt * 16 + (lane >> 2);
            const int rl1 = rl0 + 8;
            const float s0c = sc[rl0], b0c = bi[rl0];
            const float s1c = sc[rl1], b1c = bi[rl1];
            float acc0 = 0.f, acc1 = 0.f;
            #pragma unroll
            for (int nt = 0; nt < 7; nt++) {
                #pragma unroll
                for (int jj = 0; jj < 2; jj++) {
                    int p = pbase + nt * 8 + jj;
                    if (p < P_) {
                        float h0 = d[mt][nt][jj] * s0c + b0c;
                        acc0 += h0 * fminf(fmaxf(h0 + 3.f, 0.f), 6.f) * (1.f / 6.f);
                        float h1 = d[mt][nt][2 + jj] * s1c + b1c;
                        acc1 += h1 * fminf(fmaxf(h1 + 3.f, 0.f), 6.f) * (1.f / 6.f);
                    }
                }
            }
            acc0 += __shfl_xor_sync(0xFFFFFFFFu, acc0, 1);
            acc0 += __shfl_xor_sync(0xFFFFFFFFu, acc0, 2);
            acc1 += __shfl_xor_sync(0xFFFFFFFFu, acc1, 1);
            acc1 += __shfl_xor_sync(0xFFFFFFFFu, acc1, 2);
            if ((lane & 3) == 0) {
                part[(np * 2 + wn) * 128 + rl0] += acc0;
                part[(np * 2 + wn) * 128 + rl1] += acc1;
            }
        }
    }

    __syncthreads();
    if (tid < 128)
        g_hmean[b * R_ + rbase + tid] = (part[tid] + part[128 + tid] +
                                         part[256 + tid] + part[384 + tid]) * (1.f / (float)P_);
}

// ============================================================================
// Kernel B: logits = hmean @ w2^T ; BN2 ; sigmoid ; ROI coords
// ============================================================================
__global__ void kernelB(const float* __restrict__ w2, const float* __restrict__ g2,
                        const float* __restrict__ b2, const float* __restrict__ m2,
                        const float* __restrict__ v2) {
    const int b = blockIdx.x;
    const int lane = threadIdx.x;
    const float* h = g_hmean + b * R_;

    float lg[6];
    #pragma unroll
    for (int j = 0; j < 6; j++) {
        float s = 0.f;
        #pragma unroll
        for (int r = lane; r < R_; r += 32) s += h[r] * w2[j * R_ + r];
        #pragma unroll
        for (int off = 16; off; off >>= 1) s += __shfl_xor_sync(0xFFFFFFFFu, s, off);
        lg[j] = s;
    }
    if (lane < 6) {
        const int j = lane;
        float sf = g2[j] * rsqrtf(v2[j] + EPSV);
        float l  = (lg[j] - m2[j]) * sf + b2[j];
        float sig = 1.f / (1.f + expf(-l));
        const float SC[3] = {7.f, 7.f, 4.f};
        float outv = (j < 3) ? (0.5f * sig * SC[j])
                             : ((1.f - 0.5f * sig) * SC[j - 3]);
        g_coords[b * 6 + j] = outv;
    }
}

// ============================================================================
// Kernel C: ROI align 3D from g_xh (fp16). Block = (32-ch tile, batch).
// ============================================================================
__global__ void __launch_bounds__(256)
kernelC(float* __restrict__ out) {
    __shared__ float xs[32 * 200];
    __shared__ int   ilo[13], ihi[13];
    __shared__ float ww0[13], ww1[13];

    const int tid = threadIdx.x;
    const int b   = blockIdx.y;
    const int cc  = blockIdx.x * 32;

    const __half* xh = g_xh + (size_t)b * P_ * C_;

    // stage channel tile: read x_h[p][cc..cc+31], store xs[c][p] f32
    for (int i = tid; i < P_ * 8; i += 256) {
        int p = i >> 3, cq = i & 7;                 // 4 fp16 per load
        uint2 w = reinterpret_cast<const uint2*>(xh + (size_t)p * C_ + cc)[cq];
        __half2 h0 = *reinterpret_cast<__half2*>(&w.x);
        __half2 h1 = *reinterpret_cast<__half2*>(&w.y);
        int c = cq * 4;
        xs[(c + 0) * 200 + p] = __low2float(h0);
        xs[(c + 1) * 200 + p] = __high2float(h0);
        xs[(c + 2) * 200 + p] = __low2float(h1);
        xs[(c + 3) * 200 + p] = __high2float(h1);
    }

    if (tid < 13) {
        int axis = (tid < 5) ? 0 : ((tid < 10) ? 1 : 2);
        int i    = (tid < 5) ? tid : ((tid < 10) ? tid - 5 : tid - 10);
        int   n    = (axis == 2) ? 3 : 5;
        float size = (axis == 2) ? 4.f : 7.f;
        float s = g_coords[b * 6 + axis];
        float e = g_coords[b * 6 + 3 + axis];
        float bin = (e - s) / (float)n;
        float c = s + ((float)i + 0.5f) * bin;
        float valid = (c >= -1.f && c <= size) ? 1.f : 0.f;
        c = fminf(fmaxf(c, 0.f), size - 1.f);
        int lo = (int)floorf(c);
        int hi = min(lo + 1, (int)size - 1);
        float f = c - (float)lo;
        ilo[tid] = lo; ihi[tid] = hi;
        ww0[tid] = (1.f - f) * valid;
        ww1[tid] = f * valid;
    }
    __syncthreads();

    for (int o = tid; o < 32 * 75; o += 256) {
        int c = o / 75, p = o - c * 75;
        int ot = p / 25, r = p - ot * 25;
        int oy = r / 5,  ox = r - oy * 5;

        int t0 = ilo[10 + ot], t1 = ihi[10 + ot];
        float tw0 = ww0[10 + ot], tw1 = ww1[10 + ot];
        int y0 = ilo[5 + oy], y1 = ihi[5 + oy];
        float yw0 = ww0[5 + oy], yw1 = ww1[5 + oy];
        int x0 = ilo[ox], x1 = ihi[ox];
        float xw0 = ww0[ox], xw1 = ww1[ox];

        const float* base = xs + c * 200;
        float v00 = xw0 * base[t0 * 49 + y0 * 7 + x0] + xw1 * base[t0 * 49 + y0 * 7 + x1];
        float v01 = xw0 * base[t0 * 49 + y1 * 7 + x0] + xw1 * base[t0 * 49 + y1 * 7 + x1];
        float v10 = xw0 * base[t1 * 49 + y0 * 7 + x0] + xw1 * base[t1 * 49 + y0 * 7 + x1];
        float v11 = xw0 * base[t1 * 49 + y1 * 7 + x0] + xw1 * base[t1 * 49 + y1 * 7 + x1];
        float v = tw0 * (yw0 * v00 + yw1 * v01) + tw1 * (yw0 * v10 + yw1 * v11);

        out[((size_t)(b * C_ + cc + c)) * 75 + p] = v;
    }
}

// ============================================================================
extern "C" void kernel_launch(void* const* d_in, const int* in_sizes, int n_in,
                              void* d_out, int out_size) {
    const float* x  = (const float*)d_in[0];
    const float* w1 = (const float*)d_in[1];
    const float* g1 = (const float*)d_in[2];
    const float* b1 = (const float*)d_in[3];
    const float* m1 = (const float*)d_in[4];
    const float* v1 = (const float*)d_in[5];
    const float* w2 = (const float*)d_in[6];
    const float* g2 = (const float*)d_in[7];
    const float* b2 = (const float*)d_in[8];
    const float* m2 = (const float*)d_in[9];
    const float* v2 = (const float*)d_in[10];
    float* out = (float*)d_out;

    cudaFuncSetAttribute(kernelA, cudaFuncAttributeMaxDynamicSharedMemorySize,
                         (int)SMEM_A_TOTAL);

    dim3 gridP(17, B_);
    kernelP<<<gridP, 256>>>(x, w1);
    dim3 gridA(2, B_);
    kernelA<<<gridA, 256, SMEM_A_TOTAL>>>(g1, b1, m1, v1);
    kernelB<<<B_, 32>>>(w2, g2, b2, m2, v2);
    dim3 gridC(C_ / 32, B_);
    kernelC<<<gridC, 256>>>(out);
}

// round 7
// speedup vs baseline: 3.3754x; 1.0570x over previous
#include <cuda_runtime.h>
#include <cuda_fp16.h>
#include <cstdint>
#include <math.h>

// Problem constants
#define B_   128
#define C_   1024
#define R_   256
#define T_   4
#define H_   7
#define W_   7
#define P_   196     // T*H*W
#define EPSV 1e-5f

// ---------------- intermediates (device globals; no allocation allowed) ----
__device__ float  g_hmean[B_ * R_];
__device__ float  g_coords[B_ * 6];
__device__ __half g_xh[(size_t)B_ * P_ * C_];   // x transposed: [b][p][c] fp16
__device__ __half g_w1h[R_ * C_];               // w1 fp16: [r][c]

// ---------------- helpers ---------------------------------------------------
__device__ __forceinline__ void mma_f16(float& d0, float& d1, float& d2, float& d3,
                                        uint32_t a0, uint32_t a1, uint32_t a2, uint32_t a3,
                                        uint32_t b0, uint32_t b1) {
    asm volatile(
        "mma.sync.aligned.m16n8k16.row.col.f32.f16.f16.f32 "
        "{%0,%1,%2,%3}, {%4,%5,%6,%7}, {%8,%9}, {%0,%1,%2,%3};\n"
        : "+f"(d0), "+f"(d1), "+f"(d2), "+f"(d3)
        : "r"(a0), "r"(a1), "r"(a2), "r"(a3), "r"(b0), "r"(b1));
}

__device__ __forceinline__ void cp16(void* smem_dst, const void* gsrc, int srcbytes) {
    uint32_t s = (uint32_t)__cvta_generic_to_shared(smem_dst);
    asm volatile("cp.async.ca.shared.global [%0], [%1], 16, %2;\n"
                 :: "r"(s), "l"(gsrc), "r"(srcbytes));
}
__device__ __forceinline__ void cp_commit() { asm volatile("cp.async.commit_group;\n"); }
__device__ __forceinline__ void cp_wait0()  { asm volatile("cp.async.wait_group 0;\n"); }
__device__ __forceinline__ void cp_wait1()  { asm volatile("cp.async.wait_group 1;\n"); }
__device__ __forceinline__ void cp_wait2()  { asm volatile("cp.async.wait_group 2;\n"); }

// ============================================================================
// Kernel P: blockIdx.x < 16 : transpose+convert x[b][c][p] f32 -> g_xh[b][p][c]
//           blockIdx.x ==16 : convert w1 -> g_w1h (2 rows per blockIdx.y)
// ============================================================================
__global__ void __launch_bounds__(256)
kernelP(const float* __restrict__ x, const float* __restrict__ w1) {
    const int tid = threadIdx.x;
    const int b   = blockIdx.y;

    if (blockIdx.x == 16) {   // w1 convert: rows [2b, 2b+2)
        const int e0 = b * 2048;
        #pragma unroll
        for (int it = 0; it < 2; it++) {
            int idx = it * 256 + tid;
            float4 v = reinterpret_cast<const float4*>(w1 + e0)[idx];
            __half2 h0 = __floats2half2_rn(v.x, v.y);
            __half2 h1 = __floats2half2_rn(v.z, v.w);
            uint2 u;
            u.x = *reinterpret_cast<uint32_t*>(&h0);
            u.y = *reinterpret_cast<uint32_t*>(&h1);
            reinterpret_cast<uint2*>(g_w1h + e0)[idx] = u;
        }
        return;
    }

    __shared__ unsigned short xs[64 * 202];
    const int c0 = blockIdx.x * 64;

    for (int idx = tid; idx < 64 * 49; idx += 256) {
        int c = idx / 49, q = idx - c * 49;
        float4 v = reinterpret_cast<const float4*>(
                       x + ((size_t)b * C_ + c0 + c) * P_)[q];
        unsigned short* dst = xs + c * 202 + q * 4;
        dst[0] = __half_as_ushort(__float2half_rn(v.x));
        dst[1] = __half_as_ushort(__float2half_rn(v.y));
        dst[2] = __half_as_ushort(__float2half_rn(v.z));
        dst[3] = __half_as_ushort(__float2half_rn(v.w));
    }
    __syncthreads();

    uint32_t* outu = reinterpret_cast<uint32_t*>(g_xh);
    for (int idx = tid; idx < P_ * 32; idx += 256) {
        int p = idx >> 5, ch = idx & 31;
        uint32_t lo = xs[(2 * ch    ) * 202 + p];
        uint32_t hi = xs[(2 * ch + 1) * 202 + p];
        outu[((size_t)b * P_ + p) * (C_ / 2) + (c0 >> 1) + ch] = lo | (hi << 16);
    }
}

// ============================================================================
// Kernel A: GEMM  H[r,p] = sum_c w1[r,c] * x[b,c,p]   (fp16 HMMA m16n8k16)
// fused BN-affine + hardswish + mean over p  ->  g_hmean[b][r]
// CTA = (mhalf, batch): 128 r rows x 196 p (two passes of 112).
// 256 threads = 8 warps (4M x 2N), warp tile 32x56. 4-stage cp.async.
// ============================================================================
#define KC      32
#define NKC     32     // 1024/32
#define NPW     112    // N (p) columns per pass
#define SA_H    40     // A smem stride in fp16 (80 B)
#define SB_H    40     // B smem stride in fp16 (80 B)
#define ASZ     10240  // 128*80
#define BSZ     8960   // 112*80

// smem byte offsets
#define OFF_A    0
#define OFF_B    (4 * ASZ)                   // 40960
#define OFF_PART (OFF_B + 4 * BSZ)           // 76800 (512 f32)
#define OFF_SC   (OFF_PART + 2048)           // 78848 (128 f32)
#define OFF_BI   (OFF_SC + 512)              // 79360 (128 f32)
#define SMEM_A_TOTAL (OFF_BI + 512)          // 79872 B

__global__ void __launch_bounds__(256, 2)
kernelA(const float* __restrict__ g1, const float* __restrict__ b1,
        const float* __restrict__ m1, const float* __restrict__ v1) {
    extern __shared__ __align__(16) char smem[];
    float* part = reinterpret_cast<float*>(smem + OFF_PART);
    float* sc   = reinterpret_cast<float*>(smem + OFF_SC);
    float* bi   = reinterpret_cast<float*>(smem + OFF_BI);

    const int mh   = blockIdx.x;
    const int b    = blockIdx.y;
    const int tid  = threadIdx.x;
    const int lane = tid & 31;
    const int warp = tid >> 5;
    const int wm   = warp >> 1;
    const int wn   = warp & 1;
    const int rbase = mh * 128;

    part[tid]       = 0.f;
    part[tid + 256] = 0.f;
    if (tid < 128) {
        int r = rbase + tid;
        float s = g1[r] * rsqrtf(v1[r] + EPSV);
        sc[tid] = s;
        bi[tid] = b1[r] - m1[r] * s;
    }

    const __half* w1h = g_w1h;
    const __half* xh  = g_xh + (size_t)b * P_ * C_;

    #pragma unroll 1
    for (int np = 0; np < 2; np++) {
        __syncthreads();

        auto stageA = [&](int s, int kc) {
            char* base = smem + OFF_A + s * ASZ;
            #pragma unroll
            for (int it = 0; it < 2; it++) {       // 512 cp16
                int idx = it * 256 + tid;
                int row = idx >> 2, ch = idx & 3;
                cp16(base + row * 80 + ch * 16,
                     w1h + (size_t)(rbase + row) * C_ + kc + ch * 8, 16);
            }
        };
        auto stageB = [&](int s, int kc) {
            char* base = smem + OFF_B + s * BSZ;
            #pragma unroll
            for (int it = 0; it < 2; it++) {       // 448 cp16
                int idx = it * 256 + tid;
                if (idx < 448) {
                    int row = idx >> 2, ch = idx & 3;
                    int p = np * NPW + row;
                    int ok = (p < P_);
                    const __half* src = xh + (size_t)(ok ? p : 0) * C_ + kc + ch * 8;
                    cp16(base + row * 80 + ch * 16, src, ok ? 16 : 0);
                }
            }
        };

        stageA(0, 0);      stageB(0, 0);      cp_commit();
        stageA(1, KC);     stageB(1, KC);     cp_commit();
        stageA(2, 2 * KC); stageB(2, 2 * KC); cp_commit();

        float d[2][7][4];
        #pragma unroll
        for (int mt = 0; mt < 2; mt++)
            #pragma unroll
            for (int nt = 0; nt < 7; nt++)
                #pragma unroll
                for (int j = 0; j < 4; j++) d[mt][nt][j] = 0.f;

        #pragma unroll 1
        for (int kci = 0; kci < NKC; kci++) {
            if (kci + 2 < NKC)      cp_wait2();
            else if (kci + 1 < NKC) cp_wait1();
            else                    cp_wait0();
            __syncthreads();

            if (kci + 3 < NKC) {
                int nb = (kci + 3) & 3;
                stageA(nb, (kci + 3) * KC);
                stageB(nb, (kci + 3) * KC);
                cp_commit();
            }

            const __half* Aw = reinterpret_cast<const __half*>(smem + OFF_A + (kci & 3) * ASZ);
            const __half* Xs = reinterpret_cast<const __half*>(smem + OFF_B + (kci & 3) * BSZ);

            #pragma unroll
            for (int kk = 0; kk < 2; kk++) {
                const int acol = kk * 16 + (lane & 3) * 2;
                uint32_t a[2][4];
                const int ar = wm * 32 + (lane >> 2);
                #pragma unroll
                for (int mt = 0; mt < 2; mt++) {
                    const __half* p0 = Aw + (ar + mt * 16) * SA_H + acol;
                    const __half* p1 = Aw + (ar + mt * 16 + 8) * SA_H + acol;
                    a[mt][0] = *reinterpret_cast<const uint32_t*>(p0);
                    a[mt][1] = *reinterpret_cast<const uint32_t*>(p1);
                    a[mt][2] = *reinterpret_cast<const uint32_t*>(p0 + 8);
                    a[mt][3] = *reinterpret_cast<const uint32_t*>(p1 + 8);
                }
                uint32_t bb[7][2];
                const int bn = wn * 56 + (lane >> 2);
                #pragma unroll
                for (int nt = 0; nt < 7; nt++) {
                    const __half* pb = Xs + (bn + nt * 8) * SB_H + acol;
                    bb[nt][0] = *reinterpret_cast<const uint32_t*>(pb);
                    bb[nt][1] = *reinterpret_cast<const uint32_t*>(pb + 8);
                }
                #pragma unroll
                for (int mt = 0; mt < 2; mt++)
                    #pragma unroll
                    for (int nt = 0; nt < 7; nt++)
                        mma_f16(d[mt][nt][0], d[mt][nt][1], d[mt][nt][2], d[mt][nt][3],
                                a[mt][0], a[mt][1], a[mt][2], a[mt][3],
                                bb[nt][0], bb[nt][1]);
            }
        }

        // epilogue
        const int pbase = np * NPW + wn * 56 + (lane & 3) * 2;
        #pragma unroll
        for (int mt = 0; mt < 2; mt++) {
            const int rl0 = wm * 32 + mt * 16 + (lane >> 2);
            const int rl1 = rl0 + 8;
            const float s0c = sc[rl0], b0c = bi[rl0];
            const float s1c = sc[rl1], b1c = bi[rl1];
            float acc0 = 0.f, acc1 = 0.f;
            #pragma unroll
            for (int nt = 0; nt < 7; nt++) {
                #pragma unroll
                for (int jj = 0; jj < 2; jj++) {
                    int p = pbase + nt * 8 + jj;
                    if (p < P_) {
                        float h0 = d[mt][nt][jj] * s0c + b0c;
                        acc0 += h0 * fminf(fmaxf(h0 + 3.f, 0.f), 6.f) * (1.f / 6.f);
                        float h1 = d[mt][nt][2 + jj] * s1c + b1c;
                        acc1 += h1 * fminf(fmaxf(h1 + 3.f, 0.f), 6.f) * (1.f / 6.f);
                    }
                }
            }
            acc0 += __shfl_xor_sync(0xFFFFFFFFu, acc0, 1);
            acc0 += __shfl_xor_sync(0xFFFFFFFFu, acc0, 2);
            acc1 += __shfl_xor_sync(0xFFFFFFFFu, acc1, 1);
            acc1 += __shfl_xor_sync(0xFFFFFFFFu, acc1, 2);
            if ((lane & 3) == 0) {
                part[(np * 2 + wn) * 128 + rl0] += acc0;
                part[(np * 2 + wn) * 128 + rl1] += acc1;
            }
        }
    }

    __syncthreads();
    if (tid < 128)
        g_hmean[b * R_ + rbase + tid] = (part[tid] + part[128 + tid] +
                                         part[256 + tid] + part[384 + tid]) * (1.f / (float)P_);
}

// ============================================================================
// Kernel B: logits = hmean @ w2^T ; BN2 ; sigmoid ; ROI coords
// ============================================================================
__global__ void kernelB(const float* __restrict__ w2, const float* __restrict__ g2,
                        const float* __restrict__ b2, const float* __restrict__ m2,
                        const float* __restrict__ v2) {
    const int b = blockIdx.x;
    const int lane = threadIdx.x;
    const float* h = g_hmean + b * R_;

    float lg[6];
    #pragma unroll
    for (int j = 0; j < 6; j++) {
        float s = 0.f;
        #pragma unroll
        for (int r = lane; r < R_; r += 32) s += h[r] * w2[j * R_ + r];
        #pragma unroll
        for (int off = 16; off; off >>= 1) s += __shfl_xor_sync(0xFFFFFFFFu, s, off);
        lg[j] = s;
    }
    if (lane < 6) {
        const int j = lane;
        float sf = g2[j] * rsqrtf(v2[j] + EPSV);
        float l  = (lg[j] - m2[j]) * sf + b2[j];
        float sig = 1.f / (1.f + expf(-l));
        const float SC[3] = {7.f, 7.f, 4.f};
        float outv = (j < 3) ? (0.5f * sig * SC[j])
                             : ((1.f - 0.5f * sig) * SC[j - 3]);
        g_coords[b * 6 + j] = outv;
    }
}

// ============================================================================
// Kernel C: ROI align 3D from g_xh. Block = (32-ch tile, batch), 256 thr.
// xs[p][36] spatial-major tile; warp-uniform output point, lane = channel.
// Conflict-free LDS taps; coalesced STG via obuf transpose.
// ============================================================================
__global__ void __launch_bounds__(256)
kernelC(float* __restrict__ out) {
    __shared__ float xs[P_ * 36];      // [p][36] : 28224 B
    __shared__ float obuf[75 * 33];    // [o][33] : 9900 B
    __shared__ int   ilo[13], ihi[13];
    __shared__ float ww0[13], ww1[13];

    const int tid  = threadIdx.x;
    const int lane = tid & 31;
    const int warp = tid >> 5;
    const int b    = blockIdx.y;
    const int cc   = blockIdx.x * 32;

    const __half* xh = g_xh + (size_t)b * P_ * C_;

    // stage tile: xs[p][0..31] = x_h[p][cc..cc+31] (f32)
    for (int i = tid; i < P_ * 8; i += 256) {
        int p = i >> 3, cq = i & 7;
        uint2 w = reinterpret_cast<const uint2*>(xh + (size_t)p * C_ + cc)[cq];
        __half2 h0 = *reinterpret_cast<__half2*>(&w.x);
        __half2 h1 = *reinterpret_cast<__half2*>(&w.y);
        float4 f;
        f.x = __low2float(h0);  f.y = __high2float(h0);
        f.z = __low2float(h1);  f.w = __high2float(h1);
        *reinterpret_cast<float4*>(xs + p * 36 + cq * 4) = f;
    }

    // axis tables: 0..4 = x (size 7, n 5), 5..9 = y (7,5), 10..12 = t (4,3)
    if (tid < 13) {
        int axis = (tid < 5) ? 0 : ((tid < 10) ? 1 : 2);
        int i    = (tid < 5) ? tid : ((tid < 10) ? tid - 5 : tid - 10);
        int   n    = (axis == 2) ? 3 : 5;
        float size = (axis == 2) ? 4.f : 7.f;
        float s = g_coords[b * 6 + axis];
        float e = g_coords[b * 6 + 3 + axis];
        float bin = (e - s) / (float)n;
        float c = s + ((float)i + 0.5f) * bin;
        float valid = (c >= -1.f && c <= size) ? 1.f : 0.f;
        c = fminf(fmaxf(c, 0.f), size - 1.f);
        int lo = (int)floorf(c);
        int hi = min(lo + 1, (int)size - 1);
        float f = c - (float)lo;
        ilo[tid] = lo; ihi[tid] = hi;
        ww0[tid] = (1.f - f) * valid;
        ww1[tid] = f * valid;
    }
    __syncthreads();

    // gather: each warp owns output point o; lanes = 32 channels
    #pragma unroll 1
    for (int o = warp; o < 75; o += 8) {
        int ot = o / 25, rr = o - ot * 25;
        int oy = rr / 5, ox = rr - oy * 5;

        int rt0 = ilo[10 + ot] * 49, rt1 = ihi[10 + ot] * 49;
        float tw0 = ww0[10 + ot],  tw1 = ww1[10 + ot];
        int ry0 = ilo[5 + oy] * 7, ry1 = ihi[5 + oy] * 7;
        float yw0 = ww0[5 + oy],   yw1 = ww1[5 + oy];
        int x0 = ilo[ox], x1 = ihi[ox];
        float xw0 = ww0[ox], xw1 = ww1[ox];

        const float* bs = xs + lane;
        float v000 = bs[(rt0 + ry0 + x0) * 36];
        float v001 = bs[(rt0 + ry0 + x1) * 36];
        float v010 = bs[(rt0 + ry1 + x0) * 36];
        float v011 = bs[(rt0 + ry1 + x1) * 36];
        float v100 = bs[(rt1 + ry0 + x0) * 36];
        float v101 = bs[(rt1 + ry0 + x1) * 36];
        float v110 = bs[(rt1 + ry1 + x0) * 36];
        float v111 = bs[(rt1 + ry1 + x1) * 36];

        float v = tw0 * (yw0 * (xw0 * v000 + xw1 * v001) +
                         yw1 * (xw0 * v010 + xw1 * v011)) +
                  tw1 * (yw0 * (xw0 * v100 + xw1 * v101) +
                         yw1 * (xw0 * v110 + xw1 * v111));
        obuf[o * 33 + lane] = v;
    }
    __syncthreads();

    // write-out: coalesced out[b][cc+c][o]
    for (int i = tid; i < 32 * 75; i += 256) {
        int c = i / 75, o = i - c * 75;
        out[((size_t)(b * C_ + cc + c)) * 75 + o] = obuf[o * 33 + c];
    }
}

// ============================================================================
extern "C" void kernel_launch(void* const* d_in, const int* in_sizes, int n_in,
                              void* d_out, int out_size) {
    const float* x  = (const float*)d_in[0];
    const float* w1 = (const float*)d_in[1];
    const float* g1 = (const float*)d_in[2];
    const float* b1 = (const float*)d_in[3];
    const float* m1 = (const float*)d_in[4];
    const float* v1 = (const float*)d_in[5];
    const float* w2 = (const float*)d_in[6];
    const float* g2 = (const float*)d_in[7];
    const float* b2 = (const float*)d_in[8];
    const float* m2 = (const float*)d_in[9];
    const float* v2 = (const float*)d_in[10];
    float* out = (float*)d_out;

    cudaFuncSetAttribute(kernelA, cudaFuncAttributeMaxDynamicSharedMemorySize,
                         (int)SMEM_A_TOTAL);

    dim3 gridP(17, B_);
    kernelP<<<gridP, 256>>>(x, w1);
    dim3 gridA(2, B_);
    kernelA<<<gridA, 256, SMEM_A_TOTAL>>>(g1, b1, m1, v1);
    kernelB<<<B_, 32>>>(w2, g2, b2, m2, v2);
    dim3 gridC(C_ / 32, B_);
    kernelC<<<gridC, 256>>>(out);
}

// round 8
// speedup vs baseline: 3.6689x; 1.0870x over previous
#include <cuda_runtime.h>
#include <cuda_fp16.h>
#include <cstdint>
#include <math.h>

// Problem constants
#define B_   128
#define C_   1024
#define R_   256
#define T_   4
#define H_   7
#define W_   7
#define P_   196     // T*H*W
#define EPSV 1e-5f

// ---------------- intermediates (device globals; no allocation allowed) ----
__device__ float  g_hmean[B_ * R_];
__device__ float  g_coords[B_ * 6];
__device__ __half g_xh[(size_t)B_ * P_ * C_];   // x transposed: [b][p][c] fp16
__device__ __half g_w1h[R_ * C_];               // w1 fp16: [r][c]

// ---------------- helpers ---------------------------------------------------
__device__ __forceinline__ void mma_f16(float& d0, float& d1, float& d2, float& d3,
                                        uint32_t a0, uint32_t a1, uint32_t a2, uint32_t a3,
                                        uint32_t b0, uint32_t b1) {
    asm volatile(
        "mma.sync.aligned.m16n8k16.row.col.f32.f16.f16.f32 "
        "{%0,%1,%2,%3}, {%4,%5,%6,%7}, {%8,%9}, {%0,%1,%2,%3};\n"
        : "+f"(d0), "+f"(d1), "+f"(d2), "+f"(d3)
        : "r"(a0), "r"(a1), "r"(a2), "r"(a3), "r"(b0), "r"(b1));
}

__device__ __forceinline__ void cp16(void* smem_dst, const void* gsrc, int srcbytes) {
    uint32_t s = (uint32_t)__cvta_generic_to_shared(smem_dst);
    asm volatile("cp.async.ca.shared.global [%0], [%1], 16, %2;\n"
                 :: "r"(s), "l"(gsrc), "r"(srcbytes));
}
__device__ __forceinline__ void cp_commit() { asm volatile("cp.async.commit_group;\n"); }
__device__ __forceinline__ void cp_wait0()  { asm volatile("cp.async.wait_group 0;\n"); }
__device__ __forceinline__ void cp_wait1()  { asm volatile("cp.async.wait_group 1;\n"); }
__device__ __forceinline__ void cp_wait2()  { asm volatile("cp.async.wait_group 2;\n"); }

// ============================================================================
// Kernel P: blockIdx.x < 16 : transpose+convert x[b][c][p] f32 -> g_xh[b][p][c]
//           blockIdx.x ==16 : convert w1 -> g_w1h (2 rows per blockIdx.y)
// ============================================================================
__global__ void __launch_bounds__(256)
kernelP(const float* __restrict__ x, const float* __restrict__ w1) {
    const int tid = threadIdx.x;
    const int b   = blockIdx.y;

    if (blockIdx.x == 16) {   // w1 convert: rows [2b, 2b+2)
        const int e0 = b * 2048;
        #pragma unroll
        for (int it = 0; it < 2; it++) {
            int idx = it * 256 + tid;
            float4 v = reinterpret_cast<const float4*>(w1 + e0)[idx];
            __half2 h0 = __floats2half2_rn(v.x, v.y);
            __half2 h1 = __floats2half2_rn(v.z, v.w);
            uint2 u;
            u.x = *reinterpret_cast<uint32_t*>(&h0);
            u.y = *reinterpret_cast<uint32_t*>(&h1);
            reinterpret_cast<uint2*>(g_w1h + e0)[idx] = u;
        }
        return;
    }

    __shared__ unsigned short xs[64 * 202];
    const int c0 = blockIdx.x * 64;

    for (int idx = tid; idx < 64 * 49; idx += 256) {
        int c = idx / 49, q = idx - c * 49;
        float4 v = reinterpret_cast<const float4*>(
                       x + ((size_t)b * C_ + c0 + c) * P_)[q];
        unsigned short* dst = xs + c * 202 + q * 4;
        dst[0] = __half_as_ushort(__float2half_rn(v.x));
        dst[1] = __half_as_ushort(__float2half_rn(v.y));
        dst[2] = __half_as_ushort(__float2half_rn(v.z));
        dst[3] = __half_as_ushort(__float2half_rn(v.w));
    }
    __syncthreads();

    uint32_t* outu = reinterpret_cast<uint32_t*>(g_xh);
    for (int idx = tid; idx < P_ * 32; idx += 256) {
        int p = idx >> 5, ch = idx & 31;
        uint32_t lo = xs[(2 * ch    ) * 202 + p];
        uint32_t hi = xs[(2 * ch + 1) * 202 + p];
        outu[((size_t)b * P_ + p) * (C_ / 2) + (c0 >> 1) + ch] = lo | (hi << 16);
    }
}

// ============================================================================
// Kernel A: GEMM  H[r,p] = sum_c w1[r,c] * x[b,c,p]   (fp16 HMMA m16n8k16)
// fused BN-affine + hardswish + mean over p  ->  g_hmean[b][r]
// CTA = (mhalf, batch): 128 r rows x 196 p (two passes of 112).
// 256 threads = 8 warps (4M x 2N), warp tile 32x56. 4-stage cp.async.
// ============================================================================
#define KC      32
#define NKC     32     // 1024/32
#define NPW     112    // N (p) columns per pass
#define SA_H    40     // A smem stride in fp16 (80 B)
#define SB_H    40     // B smem stride in fp16 (80 B)
#define ASZ     10240  // 128*80
#define BSZ     8960   // 112*80

// smem byte offsets
#define OFF_A    0
#define OFF_B    (4 * ASZ)                   // 40960
#define OFF_PART (OFF_B + 4 * BSZ)           // 76800 (512 f32)
#define OFF_SC   (OFF_PART + 2048)           // 78848 (128 f32)
#define OFF_BI   (OFF_SC + 512)              // 79360 (128 f32)
#define SMEM_A_TOTAL (OFF_BI + 512)          // 79872 B

__global__ void __launch_bounds__(256, 2)
kernelA(const float* __restrict__ g1, const float* __restrict__ b1,
        const float* __restrict__ m1, const float* __restrict__ v1) {
    extern __shared__ __align__(16) char smem[];
    float* part = reinterpret_cast<float*>(smem + OFF_PART);
    float* sc   = reinterpret_cast<float*>(smem + OFF_SC);
    float* bi   = reinterpret_cast<float*>(smem + OFF_BI);

    const int mh   = blockIdx.x;
    const int b    = blockIdx.y;
    const int tid  = threadIdx.x;
    const int lane = tid & 31;
    const int warp = tid >> 5;
    const int wm   = warp >> 1;
    const int wn   = warp & 1;
    const int rbase = mh * 128;

    part[tid]       = 0.f;
    part[tid + 256] = 0.f;
    if (tid < 128) {
        int r = rbase + tid;
        float s = g1[r] * rsqrtf(v1[r] + EPSV);
        sc[tid] = s;
        bi[tid] = b1[r] - m1[r] * s;
    }

    const __half* w1h = g_w1h;
    const __half* xh  = g_xh + (size_t)b * P_ * C_;

    #pragma unroll 1
    for (int np = 0; np < 2; np++) {
        __syncthreads();

        auto stageA = [&](int s, int kc) {
            char* base = smem + OFF_A + s * ASZ;
            #pragma unroll
            for (int it = 0; it < 2; it++) {       // 512 cp16
                int idx = it * 256 + tid;
                int row = idx >> 2, ch = idx & 3;
                cp16(base + row * 80 + ch * 16,
                     w1h + (size_t)(rbase + row) * C_ + kc + ch * 8, 16);
            }
        };
        auto stageB = [&](int s, int kc) {
            char* base = smem + OFF_B + s * BSZ;
            #pragma unroll
            for (int it = 0; it < 2; it++) {       // 448 cp16
                int idx = it * 256 + tid;
                if (idx < 448) {
                    int row = idx >> 2, ch = idx & 3;
                    int p = np * NPW + row;
                    int ok = (p < P_);
                    const __half* src = xh + (size_t)(ok ? p : 0) * C_ + kc + ch * 8;
                    cp16(base + row * 80 + ch * 16, src, ok ? 16 : 0);
                }
            }
        };

        stageA(0, 0);      stageB(0, 0);      cp_commit();
        stageA(1, KC);     stageB(1, KC);     cp_commit();
        stageA(2, 2 * KC); stageB(2, 2 * KC); cp_commit();

        float d[2][7][4];
        #pragma unroll
        for (int mt = 0; mt < 2; mt++)
            #pragma unroll
            for (int nt = 0; nt < 7; nt++)
                #pragma unroll
                for (int j = 0; j < 4; j++) d[mt][nt][j] = 0.f;

        #pragma unroll 1
        for (int kci = 0; kci < NKC; kci++) {
            if (kci + 2 < NKC)      cp_wait2();
            else if (kci + 1 < NKC) cp_wait1();
            else                    cp_wait0();
            __syncthreads();

            if (kci + 3 < NKC) {
                int nb = (kci + 3) & 3;
                stageA(nb, (kci + 3) * KC);
                stageB(nb, (kci + 3) * KC);
                cp_commit();
            }

            const __half* Aw = reinterpret_cast<const __half*>(smem + OFF_A + (kci & 3) * ASZ);
            const __half* Xs = reinterpret_cast<const __half*>(smem + OFF_B + (kci & 3) * BSZ);

            #pragma unroll
            for (int kk = 0; kk < 2; kk++) {
                const int acol = kk * 16 + (lane & 3) * 2;
                uint32_t a[2][4];
                const int ar = wm * 32 + (lane >> 2);
                #pragma unroll
                for (int mt = 0; mt < 2; mt++) {
                    const __half* p0 = Aw + (ar + mt * 16) * SA_H + acol;
                    const __half* p1 = Aw + (ar + mt * 16 + 8) * SA_H + acol;
                    a[mt][0] = *reinterpret_cast<const uint32_t*>(p0);
                    a[mt][1] = *reinterpret_cast<const uint32_t*>(p1);
                    a[mt][2] = *reinterpret_cast<const uint32_t*>(p0 + 8);
                    a[mt][3] = *reinterpret_cast<const uint32_t*>(p1 + 8);
                }
                uint32_t bb[7][2];
                const int bn = wn * 56 + (lane >> 2);
                #pragma unroll
                for (int nt = 0; nt < 7; nt++) {
                    const __half* pb = Xs + (bn + nt * 8) * SB_H + acol;
                    bb[nt][0] = *reinterpret_cast<const uint32_t*>(pb);
                    bb[nt][1] = *reinterpret_cast<const uint32_t*>(pb + 8);
                }
                #pragma unroll
                for (int mt = 0; mt < 2; mt++)
                    #pragma unroll
                    for (int nt = 0; nt < 7; nt++)
                        mma_f16(d[mt][nt][0], d[mt][nt][1], d[mt][nt][2], d[mt][nt][3],
                                a[mt][0], a[mt][1], a[mt][2], a[mt][3],
                                bb[nt][0], bb[nt][1]);
            }
        }

        // epilogue
        const int pbase = np * NPW + wn * 56 + (lane & 3) * 2;
        #pragma unroll
        for (int mt = 0; mt < 2; mt++) {
            const int rl0 = wm * 32 + mt * 16 + (lane >> 2);
            const int rl1 = rl0 + 8;
            const float s0c = sc[rl0], b0c = bi[rl0];
            const float s1c = sc[rl1], b1c = bi[rl1];
            float acc0 = 0.f, acc1 = 0.f;
            #pragma unroll
            for (int nt = 0; nt < 7; nt++) {
                #pragma unroll
                for (int jj = 0; jj < 2; jj++) {
                    int p = pbase + nt * 8 + jj;
                    if (p < P_) {
                        float h0 = d[mt][nt][jj] * s0c + b0c;
                        acc0 += h0 * fminf(fmaxf(h0 + 3.f, 0.f), 6.f) * (1.f / 6.f);
                        float h1 = d[mt][nt][2 + jj] * s1c + b1c;
                        acc1 += h1 * fminf(fmaxf(h1 + 3.f, 0.f), 6.f) * (1.f / 6.f);
                    }
                }
            }
            acc0 += __shfl_xor_sync(0xFFFFFFFFu, acc0, 1);
            acc0 += __shfl_xor_sync(0xFFFFFFFFu, acc0, 2);
            acc1 += __shfl_xor_sync(0xFFFFFFFFu, acc1, 1);
            acc1 += __shfl_xor_sync(0xFFFFFFFFu, acc1, 2);
            if ((lane & 3) == 0) {
                part[(np * 2 + wn) * 128 + rl0] += acc0;
                part[(np * 2 + wn) * 128 + rl1] += acc1;
            }
        }
    }

    __syncthreads();
    if (tid < 128)
        g_hmean[b * R_ + rbase + tid] = (part[tid] + part[128 + tid] +
                                         part[256 + tid] + part[384 + tid]) * (1.f / (float)P_);
}

// ============================================================================
// Kernel B: logits = hmean @ w2^T ; BN2 ; sigmoid ; ROI coords
// ============================================================================
__global__ void kernelB(const float* __restrict__ w2, const float* __restrict__ g2,
                        const float* __restrict__ b2, const float* __restrict__ m2,
                        const float* __restrict__ v2) {
    const int b = blockIdx.x;
    const int lane = threadIdx.x;
    const float* h = g_hmean + b * R_;

    float lg[6];
    #pragma unroll
    for (int j = 0; j < 6; j++) {
        float s = 0.f;
        #pragma unroll
        for (int r = lane; r < R_; r += 32) s += h[r] * w2[j * R_ + r];
        #pragma unroll
        for (int off = 16; off; off >>= 1) s += __shfl_xor_sync(0xFFFFFFFFu, s, off);
        lg[j] = s;
    }
    if (lane < 6) {
        const int j = lane;
        float sf = g2[j] * rsqrtf(v2[j] + EPSV);
        float l  = (lg[j] - m2[j]) * sf + b2[j];
        float sig = 1.f / (1.f + expf(-l));
        const float SC[3] = {7.f, 7.f, 4.f};
        float outv = (j < 3) ? (0.5f * sig * SC[j])
                             : ((1.f - 0.5f * sig) * SC[j - 3]);
        g_coords[b * 6 + j] = outv;
    }
}

// ============================================================================
// Kernel C: ROI align 3D from g_xh. Block = (64-ch tile, batch), 256 thr.
// fp16 tile xs[p][64] (raw copy), precomputed tap tables (75 x 8 w/idx),
// warp = output point, lane = 2 channels (half2 taps).
// ============================================================================
__global__ void __launch_bounds__(256)
kernelC(float* __restrict__ out) {
    __shared__ __half xs[P_ * 64];       // 25088 B
    __shared__ float  obuf[75 * 66];     // 19800 B
    __shared__ float  w8[75 * 8];        // 2400 B
    __shared__ short  idx8[75 * 8];      // 1200 B

    const int tid  = threadIdx.x;
    const int lane = tid & 31;
    const int warp = tid >> 5;
    const int b    = blockIdx.y;
    const int cc   = blockIdx.x * 64;

    const __half* xh = g_xh + (size_t)b * P_ * C_;

    // stage tile: raw uint4 copy of x_h[p][cc..cc+63]  (1568 x 16B)
    for (int i = tid; i < P_ * 8; i += 256) {
        int p = i >> 3, q = i & 7;
        uint4 v = reinterpret_cast<const uint4*>(xh + (size_t)p * C_ + cc)[q];
        *reinterpret_cast<uint4*>(xs + p * 64 + q * 8) = v;
    }

    // tap tables: one thread per output point computes 8 (weight, index)
    if (tid < 75) {
        const int ot = tid / 25, rr = tid % 25;
        const int oy = rr / 5,   ox = rr - oy * 5;

        float cs[6];
        #pragma unroll
        for (int j = 0; j < 6; j++) cs[j] = g_coords[b * 6 + j];

        auto prep = [&](int axis, int i, int n, float size,
                        int& lo, int& hi, float& w0, float& w1) {
            float s = cs[axis], e = cs[3 + axis];
            float bin = (e - s) / (float)n;
            float c = s + ((float)i + 0.5f) * bin;
            float valid = (c >= -1.f && c <= size) ? 1.f : 0.f;
            c = fminf(fmaxf(c, 0.f), size - 1.f);
            lo = (int)floorf(c);
            hi = min(lo + 1, (int)size - 1);
            float f = c - (float)lo;
            w0 = (1.f - f) * valid;
            w1 = f * valid;
        };

        int xl, xh2, yl, yh2, tl, th2;
        float xw0, xw1, yw0, yw1, tw0, tw1;
        prep(0, ox, 5, 7.f, xl, xh2, xw0, xw1);
        prep(1, oy, 5, 7.f, yl, yh2, yw0, yw1);
        prep(2, ot, 3, 4.f, tl, th2, tw0, tw1);

        #pragma unroll
        for (int k = 0; k < 8; k++) {
            int ti = (k & 4) ? th2 : tl;  float tw = (k & 4) ? tw1 : tw0;
            int yi = (k & 2) ? yh2 : yl;  float yw = (k & 2) ? yw1 : yw0;
            int xi = (k & 1) ? xh2 : xl;  float xw = (k & 1) ? xw1 : xw0;
            w8[tid * 8 + k]   = tw * yw * xw;
            idx8[tid * 8 + k] = (short)(ti * 49 + yi * 7 + xi);
        }
    }
    __syncthreads();

    // gather: warp owns output point o; lane = channel pair (2 ch)
    #pragma unroll 1
    for (int o = warp; o < 75; o += 8) {
        float ax = 0.f, ay = 0.f;
        #pragma unroll
        for (int k = 0; k < 8; k++) {
            float w  = w8[o * 8 + k];
            int   id = idx8[o * 8 + k];
            __half2 h = *reinterpret_cast<const __half2*>(xs + id * 64 + lane * 2);
            float2 f = __half22float2(h);
            ax += w * f.x;
            ay += w * f.y;
        }
        *reinterpret_cast<float2*>(obuf + o * 66 + lane * 2) = make_float2(ax, ay);
    }
    __syncthreads();

    // write-out: coalesced out[b][cc+c][o]
    for (int i = tid; i < 64 * 75; i += 256) {
        int c = i / 75, o = i - c * 75;
        out[((size_t)(b * C_ + cc + c)) * 75 + o] = obuf[o * 66 + c];
    }
}

// ============================================================================
extern "C" void kernel_launch(void* const* d_in, const int* in_sizes, int n_in,
                              void* d_out, int out_size) {
    const float* x  = (const float*)d_in[0];
    const float* w1 = (const float*)d_in[1];
    const float* g1 = (const float*)d_in[2];
    const float* b1 = (const float*)d_in[3];
    const float* m1 = (const float*)d_in[4];
    const float* v1 = (const float*)d_in[5];
    const float* w2 = (const float*)d_in[6];
    const float* g2 = (const float*)d_in[7];
    const float* b2 = (const float*)d_in[8];
    const float* m2 = (const float*)d_in[9];
    const float* v2 = (const float*)d_in[10];
    float* out = (float*)d_out;

    cudaFuncSetAttribute(kernelA, cudaFuncAttributeMaxDynamicSharedMemorySize,
                         (int)SMEM_A_TOTAL);

    dim3 gridP(17, B_);
    kernelP<<<gridP, 256>>>(x, w1);
    dim3 gridA(2, B_);
    kernelA<<<gridA, 256, SMEM_A_TOTAL>>>(g1, b1, m1, v1);
    kernelB<<<B_, 32>>>(w2, g2, b2, m2, v2);
    dim3 gridC(C_ / 64, B_);
    kernelC<<<gridC, 256>>>(out);
}

// round 9
// speedup vs baseline: 4.1173x; 1.1222x over previous
#include <cuda_runtime.h>
#include <cuda_fp16.h>
#include <cstdint>
#include <math.h>

// Problem constants
#define B_   128
#define C_   1024
#define R_   256
#define T_   4
#define H_   7
#define W_   7
#define P_   196     // T*H*W
#define EPSV 1e-5f

// ---------------- intermediates (device globals; no allocation allowed) ----
__device__ float  g_hmean[B_ * R_];
__device__ float  g_coords[B_ * 6];
__device__ __half g_xh[(size_t)B_ * P_ * C_];   // x transposed: [b][p][c] fp16
__device__ __half g_w1h[R_ * C_];               // w1 fp16: [r][c]

// ---------------- helpers ---------------------------------------------------
__device__ __forceinline__ void mma_f16(float& d0, float& d1, float& d2, float& d3,
                                        uint32_t a0, uint32_t a1, uint32_t a2, uint32_t a3,
                                        uint32_t b0, uint32_t b1) {
    asm volatile(
        "mma.sync.aligned.m16n8k16.row.col.f32.f16.f16.f32 "
        "{%0,%1,%2,%3}, {%4,%5,%6,%7}, {%8,%9}, {%0,%1,%2,%3};\n"
        : "+f"(d0), "+f"(d1), "+f"(d2), "+f"(d3)
        : "r"(a0), "r"(a1), "r"(a2), "r"(a3), "r"(b0), "r"(b1));
}

__device__ __forceinline__ void ldsm_x4(uint32_t& r0, uint32_t& r1, uint32_t& r2,
                                        uint32_t& r3, uint32_t addr) {
    asm volatile("ldmatrix.sync.aligned.m8n8.x4.shared.b16 {%0,%1,%2,%3}, [%4];"
                 : "=r"(r0), "=r"(r1), "=r"(r2), "=r"(r3) : "r"(addr));
}
__device__ __forceinline__ void ldsm_x2(uint32_t& r0, uint32_t& r1, uint32_t addr) {
    asm volatile("ldmatrix.sync.aligned.m8n8.x2.shared.b16 {%0,%1}, [%2];"
                 : "=r"(r0), "=r"(r1) : "r"(addr));
}

__device__ __forceinline__ void cp16(void* smem_dst, const void* gsrc, int srcbytes) {
    uint32_t s = (uint32_t)__cvta_generic_to_shared(smem_dst);
    asm volatile("cp.async.ca.shared.global [%0], [%1], 16, %2;\n"
                 :: "r"(s), "l"(gsrc), "r"(srcbytes));
}
__device__ __forceinline__ void cp_commit() { asm volatile("cp.async.commit_group;\n"); }
__device__ __forceinline__ void cp_wait0()  { asm volatile("cp.async.wait_group 0;\n"); }
__device__ __forceinline__ void cp_wait1()  { asm volatile("cp.async.wait_group 1;\n"); }
__device__ __forceinline__ void cp_wait2()  { asm volatile("cp.async.wait_group 2;\n"); }

// ============================================================================
// Kernel P: blockIdx.x < 16 : transpose+convert x[b][c][p] f32 -> g_xh[b][p][c]
//           blockIdx.x ==16 : convert w1 -> g_w1h (2 rows per blockIdx.y)
// ============================================================================
__global__ void __launch_bounds__(256)
kernelP(const float* __restrict__ x, const float* __restrict__ w1) {
    const int tid = threadIdx.x;
    const int b   = blockIdx.y;

    if (blockIdx.x == 16) {   // w1 convert: rows [2b, 2b+2)
        const int e0 = b * 2048;
        #pragma unroll
        for (int it = 0; it < 2; it++) {
            int idx = it * 256 + tid;
            float4 v = reinterpret_cast<const float4*>(w1 + e0)[idx];
            __half2 h0 = __floats2half2_rn(v.x, v.y);
            __half2 h1 = __floats2half2_rn(v.z, v.w);
            uint2 u;
            u.x = *reinterpret_cast<uint32_t*>(&h0);
            u.y = *reinterpret_cast<uint32_t*>(&h1);
            reinterpret_cast<uint2*>(g_w1h + e0)[idx] = u;
        }
        return;
    }

    __shared__ unsigned short xs[64 * 202];
    const int c0 = blockIdx.x * 64;

    for (int idx = tid; idx < 64 * 49; idx += 256) {
        int c = idx / 49, q = idx - c * 49;
        float4 v = reinterpret_cast<const float4*>(
                       x + ((size_t)b * C_ + c0 + c) * P_)[q];
        unsigned short* dst = xs + c * 202 + q * 4;
        dst[0] = __half_as_ushort(__float2half_rn(v.x));
        dst[1] = __half_as_ushort(__float2half_rn(v.y));
        dst[2] = __half_as_ushort(__float2half_rn(v.z));
        dst[3] = __half_as_ushort(__float2half_rn(v.w));
    }
    __syncthreads();

    uint32_t* outu = reinterpret_cast<uint32_t*>(g_xh);
    for (int idx = tid; idx < P_ * 32; idx += 256) {
        int p = idx >> 5, ch = idx & 31;
        uint32_t lo = xs[(2 * ch    ) * 202 + p];
        uint32_t hi = xs[(2 * ch + 1) * 202 + p];
        outu[((size_t)b * P_ + p) * (C_ / 2) + (c0 >> 1) + ch] = lo | (hi << 16);
    }
}

// ============================================================================
// Kernel A: GEMM  H[r,p] = sum_c w1[r,c] * x[b,c,p]   (fp16 HMMA m16n8k16)
// fused BN-affine + hardswish + mean over p  ->  g_hmean[b][r]
// CTA = (mhalf, batch): 128 r rows x 196 p (two passes of 112).
// 256 threads = 8 warps (4M x 2N), warp tile 32x56. 4-stage cp.async.
// Fragment loads via ldmatrix (conflict-free with 80B row pitch).
// ============================================================================
#define KC      32
#define NKC     32     // 1024/32
#define NPW     112    // N (p) columns per pass
#define ASZ     10240  // 128 rows * 80 B
#define BSZ     8960   // 112 rows * 80 B

// smem byte offsets
#define OFF_A    0
#define OFF_B    (4 * ASZ)                   // 40960
#define OFF_PART (OFF_B + 4 * BSZ)           // 76800 (512 f32)
#define OFF_SC   (OFF_PART + 2048)           // 78848 (128 f32)
#define OFF_BI   (OFF_SC + 512)              // 79360 (128 f32)
#define SMEM_A_TOTAL (OFF_BI + 512)          // 79872 B

__global__ void __launch_bounds__(256, 2)
kernelA(const float* __restrict__ g1, const float* __restrict__ b1,
        const float* __restrict__ m1, const float* __restrict__ v1) {
    extern __shared__ __align__(16) char smem[];
    float* part = reinterpret_cast<float*>(smem + OFF_PART);
    float* sc   = reinterpret_cast<float*>(smem + OFF_SC);
    float* bi   = reinterpret_cast<float*>(smem + OFF_BI);
    const uint32_t sbase = (uint32_t)__cvta_generic_to_shared(smem);

    const int mh   = blockIdx.x;
    const int b    = blockIdx.y;
    const int tid  = threadIdx.x;
    const int lane = tid & 31;
    const int warp = tid >> 5;
    const int wm   = warp >> 1;
    const int wn   = warp & 1;
    const int rbase = mh * 128;

    part[tid]       = 0.f;
    part[tid + 256] = 0.f;
    if (tid < 128) {
        int r = rbase + tid;
        float s = g1[r] * rsqrtf(v1[r] + EPSV);
        sc[tid] = s;
        bi[tid] = b1[r] - m1[r] * s;
    }

    const __half* w1h = g_w1h;
    const __half* xh  = g_xh + (size_t)b * P_ * C_;

    // ldmatrix lane-static address components
    // A: row = wm*32 + mt*16 + (lane&15); byte col = kk*32 + (lane>>4)*16
    const uint32_t a_row  = (uint32_t)(wm * 32 + (lane & 15));
    const uint32_t a_coff = (uint32_t)((lane >> 4) << 4);
    // B x4 (nt pair): row = bn + ntp*16 + (m>>1)*8 + (lane&7); col = kk*32+(m&1)*16
    const int      m4     = lane >> 3;
    const uint32_t b_row4 = (uint32_t)(wn * 56 + ((m4 >> 1) << 3) + (lane & 7));
    const uint32_t b_coff4= (uint32_t)((m4 & 1) << 4);
    // B x2 (nt=6): row = bn + 48 + (lane&7); col = kk*32 + ((lane>>3)&1)*16
    const uint32_t b_row2 = (uint32_t)(wn * 56 + 48 + (lane & 7));
    const uint32_t b_coff2= (uint32_t)(((lane >> 3) & 1) << 4);

    #pragma unroll 1
    for (int np = 0; np < 2; np++) {
        __syncthreads();

        auto stageA = [&](int s, int kc) {
            char* base = smem + OFF_A + s * ASZ;
            #pragma unroll
            for (int it = 0; it < 2; it++) {       // 512 cp16
                int idx = it * 256 + tid;
                int row = idx >> 2, ch = idx & 3;
                cp16(base + row * 80 + ch * 16,
                     w1h + (size_t)(rbase + row) * C_ + kc + ch * 8, 16);
            }
        };
        auto stageB = [&](int s, int kc) {
            char* base = smem + OFF_B + s * BSZ;
            #pragma unroll
            for (int it = 0; it < 2; it++) {       // 448 cp16
                int idx = it * 256 + tid;
                if (idx < 448) {
                    int row = idx >> 2, ch = idx & 3;
                    int p = np * NPW + row;
                    int ok = (p < P_);
                    const __half* src = xh + (size_t)(ok ? p : 0) * C_ + kc + ch * 8;
                    cp16(base + row * 80 + ch * 16, src, ok ? 16 : 0);
                }
            }
        };

        stageA(0, 0);      stageB(0, 0);      cp_commit();
        stageA(1, KC);     stageB(1, KC);     cp_commit();
        stageA(2, 2 * KC); stageB(2, 2 * KC); cp_commit();

        float d[2][7][4];
        #pragma unroll
        for (int mt = 0; mt < 2; mt++)
            #pragma unroll
            for (int nt = 0; nt < 7; nt++)
                #pragma unroll
                for (int j = 0; j < 4; j++) d[mt][nt][j] = 0.f;

        #pragma unroll 1
        for (int kci = 0; kci < NKC; kci++) {
            if (kci + 2 < NKC)      cp_wait2();
            else if (kci + 1 < NKC) cp_wait1();
            else                    cp_wait0();
            __syncthreads();

            if (kci + 3 < NKC) {
                int nb = (kci + 3) & 3;
                stageA(nb, (kci + 3) * KC);
                stageB(nb, (kci + 3) * KC);
                cp_commit();
            }

            const uint32_t abase = sbase + OFF_A + (kci & 3) * ASZ;
            const uint32_t bbase = sbase + OFF_B + (kci & 3) * BSZ;

            #pragma unroll
            for (int kk = 0; kk < 2; kk++) {
                const uint32_t kb = (uint32_t)(kk * 32);

                uint32_t a[2][4];
                #pragma unroll
                for (int mt = 0; mt < 2; mt++)
                    ldsm_x4(a[mt][0], a[mt][1], a[mt][2], a[mt][3],
                            abase + (a_row + mt * 16) * 80 + kb + a_coff);

                uint32_t bb[7][2];
                #pragma unroll
                for (int ntp = 0; ntp < 3; ntp++)
                    ldsm_x4(bb[2 * ntp][0], bb[2 * ntp][1],
                            bb[2 * ntp + 1][0], bb[2 * ntp + 1][1],
                            bbase + (b_row4 + ntp * 16) * 80 + kb + b_coff4);
                ldsm_x2(bb[6][0], bb[6][1],
                        bbase + b_row2 * 80 + kb + b_coff2);

                #pragma unroll
                for (int mt = 0; mt < 2; mt++)
                    #pragma unroll
                    for (int nt = 0; nt < 7; nt++)
                        mma_f16(d[mt][nt][0], d[mt][nt][1], d[mt][nt][2], d[mt][nt][3],
                                a[mt][0], a[mt][1], a[mt][2], a[mt][3],
                                bb[nt][0], bb[nt][1]);
            }
        }

        // epilogue
        const int pbase = np * NPW + wn * 56 + (lane & 3) * 2;
        #pragma unroll
        for (int mt = 0; mt < 2; mt++) {
            const int rl0 = wm * 32 + mt * 16 + (lane >> 2);
            const int rl1 = rl0 + 8;
            const float s0c = sc[rl0], b0c = bi[rl0];
            const float s1c = sc[rl1], b1c = bi[rl1];
            float acc0 = 0.f, acc1 = 0.f;
            #pragma unroll
            for (int nt = 0; nt < 7; nt++) {
                #pragma unroll
                for (int jj = 0; jj < 2; jj++) {
                    int p = pbase + nt * 8 + jj;
                    if (p < P_) {
                        float h0 = d[mt][nt][jj] * s0c + b0c;
                        acc0 += h0 * fminf(fmaxf(h0 + 3.f, 0.f), 6.f) * (1.f / 6.f);
                        float h1 = d[mt][nt][2 + jj] * s1c + b1c;
                        acc1 += h1 * fminf(fmaxf(h1 + 3.f, 0.f), 6.f) * (1.f / 6.f);
                    }
                }
            }
            acc0 += __shfl_xor_sync(0xFFFFFFFFu, acc0, 1);
            acc0 += __shfl_xor_sync(0xFFFFFFFFu, acc0, 2);
            acc1 += __shfl_xor_sync(0xFFFFFFFFu, acc1, 1);
            acc1 += __shfl_xor_sync(0xFFFFFFFFu, acc1, 2);
            if ((lane & 3) == 0) {
                part[(np * 2 + wn) * 128 + rl0] += acc0;
                part[(np * 2 + wn) * 128 + rl1] += acc1;
            }
        }
    }

    __syncthreads();
    if (tid < 128)
        g_hmean[b * R_ + rbase + tid] = (part[tid] + part[128 + tid] +
                                         part[256 + tid] + part[384 + tid]) * (1.f / (float)P_);
}

// ============================================================================
// Kernel B: logits = hmean @ w2^T ; BN2 ; sigmoid ; ROI coords
// ============================================================================
__global__ void kernelB(const float* __restrict__ w2, const float* __restrict__ g2,
                        const float* __restrict__ b2, const float* __restrict__ m2,
                        const float* __restrict__ v2) {
    const int b = blockIdx.x;
    const int lane = threadIdx.x;
    const float* h = g_hmean + b * R_;

    float lg[6];
    #pragma unroll
    for (int j = 0; j < 6; j++) {
        float s = 0.f;
        #pragma unroll
        for (int r = lane; r < R_; r += 32) s += h[r] * w2[j * R_ + r];
        #pragma unroll
        for (int off = 16; off; off >>= 1) s += __shfl_xor_sync(0xFFFFFFFFu, s, off);
        lg[j] = s;
    }
    if (lane < 6) {
        const int j = lane;
        float sf = g2[j] * rsqrtf(v2[j] + EPSV);
        float l  = (lg[j] - m2[j]) * sf + b2[j];
        float sig = 1.f / (1.f + expf(-l));
        const float SC[3] = {7.f, 7.f, 4.f};
        float outv = (j < 3) ? (0.5f * sig * SC[j])
                             : ((1.f - 0.5f * sig) * SC[j - 3]);
        g_coords[b * 6 + j] = outv;
    }
}

// ============================================================================
// Kernel C: ROI align 3D from g_xh. Block = (64-ch tile, batch), 256 thr.
// fp16 tile xs[p][64] (raw copy), precomputed tap tables (75 x 8 w/idx),
// warp = output point, lane = 2 channels (half2 taps).
// ============================================================================
__global__ void __launch_bounds__(256)
kernelC(float* __restrict__ out) {
    __shared__ __half xs[P_ * 64];       // 25088 B
    __shared__ float  obuf[75 * 66];     // 19800 B
    __shared__ float  w8[75 * 8];        // 2400 B
    __shared__ short  idx8[75 * 8];      // 1200 B

    const int tid  = threadIdx.x;
    const int lane = tid & 31;
    const int warp = tid >> 5;
    const int b    = blockIdx.y;
    const int cc   = blockIdx.x * 64;

    const __half* xh = g_xh + (size_t)b * P_ * C_;

    for (int i = tid; i < P_ * 8; i += 256) {
        int p = i >> 3, q = i & 7;
        uint4 v = reinterpret_cast<const uint4*>(xh + (size_t)p * C_ + cc)[q];
        *reinterpret_cast<uint4*>(xs + p * 64 + q * 8) = v;
    }

    if (tid < 75) {
        const int ot = tid / 25, rr = tid % 25;
        const int oy = rr / 5,   ox = rr - oy * 5;

        float cs[6];
        #pragma unroll
        for (int j = 0; j < 6; j++) cs[j] = g_coords[b * 6 + j];

        auto prep = [&](int axis, int i, int n, float size,
                        int& lo, int& hi, float& w0, float& w1) {
            float s = cs[axis], e = cs[3 + axis];
            float bin = (e - s) / (float)n;
            float c = s + ((float)i + 0.5f) * bin;
            float valid = (c >= -1.f && c <= size) ? 1.f : 0.f;
            c = fminf(fmaxf(c, 0.f), size - 1.f);
            lo = (int)floorf(c);
            hi = min(lo + 1, (int)size - 1);
            float f = c - (float)lo;
            w0 = (1.f - f) * valid;
            w1 = f * valid;
        };

        int xl, xh2, yl, yh2, tl, th2;
        float xw0, xw1, yw0, yw1, tw0, tw1;
        prep(0, ox, 5, 7.f, xl, xh2, xw0, xw1);
        prep(1, oy, 5, 7.f, yl, yh2, yw0, yw1);
        prep(2, ot, 3, 4.f, tl, th2, tw0, tw1);

        #pragma unroll
        for (int k = 0; k < 8; k++) {
            int ti = (k & 4) ? th2 : tl;  float tw = (k & 4) ? tw1 : tw0;
            int yi = (k & 2) ? yh2 : yl;  float yw = (k & 2) ? yw1 : yw0;
            int xi = (k & 1) ? xh2 : xl;  float xw = (k & 1) ? xw1 : xw0;
            w8[tid * 8 + k]   = tw * yw * xw;
            idx8[tid * 8 + k] = (short)(ti * 49 + yi * 7 + xi);
        }
    }
    __syncthreads();

    #pragma unroll 1
    for (int o = warp; o < 75; o += 8) {
        float ax = 0.f, ay = 0.f;
        #pragma unroll
        for (int k = 0; k < 8; k++) {
            float w  = w8[o * 8 + k];
            int   id = idx8[o * 8 + k];
            __half2 h = *reinterpret_cast<const __half2*>(xs + id * 64 + lane * 2);
            float2 f = __half22float2(h);
            ax += w * f.x;
            ay += w * f.y;
        }
        *reinterpret_cast<float2*>(obuf + o * 66 + lane * 2) = make_float2(ax, ay);
    }
    __syncthreads();

    for (int i = tid; i < 64 * 75; i += 256) {
        int c = i / 75, o = i - c * 75;
        out[((size_t)(b * C_ + cc + c)) * 75 + o] = obuf[o * 66 + c];
    }
}

// ============================================================================
extern "C" void kernel_launch(void* const* d_in, const int* in_sizes, int n_in,
                              void* d_out, int out_size) {
    const float* x  = (const float*)d_in[0];
    const float* w1 = (const float*)d_in[1];
    const float* g1 = (const float*)d_in[2];
    const float* b1 = (const float*)d_in[3];
    const float* m1 = (const float*)d_in[4];
    const float* v1 = (const float*)d_in[5];
    const float* w2 = (const float*)d_in[6];
    const float* g2 = (const float*)d_in[7];
    const float* b2 = (const float*)d_in[8];
    const float* m2 = (const float*)d_in[9];
    const float* v2 = (const float*)d_in[10];
    float* out = (float*)d_out;

    cudaFuncSetAttribute(kernelA, cudaFuncAttributeMaxDynamicSharedMemorySize,
                         (int)SMEM_A_TOTAL);

    dim3 gridP(17, B_);
    kernelP<<<gridP, 256>>>(x, w1);
    dim3 gridA(2, B_);
    kernelA<<<gridA, 256, SMEM_A_TOTAL>>>(g1, b1, m1, v1);
    kernelB<<<B_, 32>>>(w2, g2, b2, m2, v2);
    dim3 gridC(C_ / 64, B_);
    kernelC<<<gridC, 256>>>(out);
}

// round 10
// speedup vs baseline: 4.2568x; 1.0339x over previous
#include <cuda_runtime.h>
#include <cuda_fp16.h>
#include <cstdint>
#include <math.h>

// Problem constants
#define B_   128
#define C_   1024
#define R_   256
#define T_   4
#define H_   7
#define W_   7
#define P_   196     // T*H*W
#define EPSV 1e-5f

// ---------------- intermediates (device globals; no allocation allowed) ----
__device__ float  g_hmean[B_ * R_];
__device__ float  g_coords[B_ * 6];
__device__ __half g_xh[(size_t)B_ * P_ * C_];   // x transposed: [b][p][c] fp16
__device__ __half g_w1h[R_ * C_];               // w1 fp16: [r][c]

// ---------------- helpers ---------------------------------------------------
__device__ __forceinline__ void mma_f16(float& d0, float& d1, float& d2, float& d3,
                                        uint32_t a0, uint32_t a1, uint32_t a2, uint32_t a3,
                                        uint32_t b0, uint32_t b1) {
    asm volatile(
        "mma.sync.aligned.m16n8k16.row.col.f32.f16.f16.f32 "
        "{%0,%1,%2,%3}, {%4,%5,%6,%7}, {%8,%9}, {%0,%1,%2,%3};\n"
        : "+f"(d0), "+f"(d1), "+f"(d2), "+f"(d3)
        : "r"(a0), "r"(a1), "r"(a2), "r"(a3), "r"(b0), "r"(b1));
}

__device__ __forceinline__ void ldsm_x4(uint32_t& r0, uint32_t& r1, uint32_t& r2,
                                        uint32_t& r3, uint32_t addr) {
    asm volatile("ldmatrix.sync.aligned.m8n8.x4.shared.b16 {%0,%1,%2,%3}, [%4];"
                 : "=r"(r0), "=r"(r1), "=r"(r2), "=r"(r3) : "r"(addr));
}
__device__ __forceinline__ void ldsm_x2(uint32_t& r0, uint32_t& r1, uint32_t addr) {
    asm volatile("ldmatrix.sync.aligned.m8n8.x2.shared.b16 {%0,%1}, [%2];"
                 : "=r"(r0), "=r"(r1) : "r"(addr));
}

__device__ __forceinline__ void cp16(void* smem_dst, const void* gsrc, int srcbytes) {
    uint32_t s = (uint32_t)__cvta_generic_to_shared(smem_dst);
    asm volatile("cp.async.ca.shared.global [%0], [%1], 16, %2;\n"
                 :: "r"(s), "l"(gsrc), "r"(srcbytes));
}
__device__ __forceinline__ void cp_commit() { asm volatile("cp.async.commit_group;\n"); }
__device__ __forceinline__ void cp_wait0()  { asm volatile("cp.async.wait_group 0;\n"); }
__device__ __forceinline__ void cp_wait1()  { asm volatile("cp.async.wait_group 1;\n"); }

// ============================================================================
// Kernel P: blockIdx.x < 16 : transpose+convert x[b][c][p] f32 -> g_xh[b][p][c]
//           blockIdx.x ==16 : convert w1 -> g_w1h (2 rows per blockIdx.y)
// ============================================================================
__global__ void __launch_bounds__(256)
kernelP(const float* __restrict__ x, const float* __restrict__ w1) {
    const int tid = threadIdx.x;
    const int b   = blockIdx.y;

    if (blockIdx.x == 16) {   // w1 convert: rows [2b, 2b+2)
        const int e0 = b * 2048;
        #pragma unroll
        for (int it = 0; it < 2; it++) {
            int idx = it * 256 + tid;
            float4 v = reinterpret_cast<const float4*>(w1 + e0)[idx];
            __half2 h0 = __floats2half2_rn(v.x, v.y);
            __half2 h1 = __floats2half2_rn(v.z, v.w);
            uint2 u;
            u.x = *reinterpret_cast<uint32_t*>(&h0);
            u.y = *reinterpret_cast<uint32_t*>(&h1);
            reinterpret_cast<uint2*>(g_w1h + e0)[idx] = u;
        }
        return;
    }

    __shared__ unsigned short xs[64 * 202];
    const int c0 = blockIdx.x * 64;

    for (int idx = tid; idx < 64 * 49; idx += 256) {
        int c = idx / 49, q = idx - c * 49;
        float4 v = reinterpret_cast<const float4*>(
                       x + ((size_t)b * C_ + c0 + c) * P_)[q];
        unsigned short* dst = xs + c * 202 + q * 4;
        dst[0] = __half_as_ushort(__float2half_rn(v.x));
        dst[1] = __half_as_ushort(__float2half_rn(v.y));
        dst[2] = __half_as_ushort(__float2half_rn(v.z));
        dst[3] = __half_as_ushort(__float2half_rn(v.w));
    }
    __syncthreads();

    uint32_t* outu = reinterpret_cast<uint32_t*>(g_xh);
    for (int idx = tid; idx < P_ * 32; idx += 256) {
        int p = idx >> 5, ch = idx & 31;
        uint32_t lo = xs[(2 * ch    ) * 202 + p];
        uint32_t hi = xs[(2 * ch + 1) * 202 + p];
        outu[((size_t)b * P_ + p) * (C_ / 2) + (c0 >> 1) + ch] = lo | (hi << 16);
    }
}

// ============================================================================
// Kernel A: GEMM  H[r,p] = sum_c w1[r,c] * x[b,c,p]   (fp16 HMMA m16n8k16)
// fused BN-affine + hardswish + mean over p  ->  g_hmean[b][r]
// CTA = (mhalf, batch): 128 r rows x 196 p (two passes of 112).
// 256 threads = 8 warps (4M x 2N), warp tile 32x56.
// K chunked by 64, 3-stage cp.async, ldmatrix frags (144B pitch, conflict-free).
// ============================================================================
#define KC      64
#define NKC     16     // 1024/64
#define NPW     112    // N (p) columns per pass
#define PITCH   144    // row pitch bytes (36 words: LDSM phases cover all banks)
#define ASZ     18432  // 128 rows * 144 B
#define BSZ     16128  // 112 rows * 144 B

// smem byte offsets
#define OFF_A    0
#define OFF_B    (3 * ASZ)                   // 55296
#define OFF_PART (OFF_B + 3 * BSZ)           // 103680 (512 f32)
#define OFF_SC   (OFF_PART + 2048)           // 105728 (128 f32)
#define OFF_BI   (OFF_SC + 512)              // 106240 (128 f32)
#define SMEM_A_TOTAL (OFF_BI + 512)          // 106752 B

__global__ void __launch_bounds__(256, 2)
kernelA(const float* __restrict__ g1, const float* __restrict__ b1,
        const float* __restrict__ m1, const float* __restrict__ v1) {
    extern __shared__ __align__(16) char smem[];
    float* part = reinterpret_cast<float*>(smem + OFF_PART);
    float* sc   = reinterpret_cast<float*>(smem + OFF_SC);
    float* bi   = reinterpret_cast<float*>(smem + OFF_BI);
    const uint32_t sbase = (uint32_t)__cvta_generic_to_shared(smem);

    const int mh   = blockIdx.x;
    const int b    = blockIdx.y;
    const int tid  = threadIdx.x;
    const int lane = tid & 31;
    const int warp = tid >> 5;
    const int wm   = warp >> 1;
    const int wn   = warp & 1;
    const int rbase = mh * 128;

    part[tid]       = 0.f;
    part[tid + 256] = 0.f;
    if (tid < 128) {
        int r = rbase + tid;
        float s = g1[r] * rsqrtf(v1[r] + EPSV);
        sc[tid] = s;
        bi[tid] = b1[r] - m1[r] * s;
    }

    const __half* w1h = g_w1h;
    const __half* xh  = g_xh + (size_t)b * P_ * C_;

    // ldmatrix lane-static address components
    const uint32_t a_row  = (uint32_t)(wm * 32 + (lane & 15));
    const uint32_t a_coff = (uint32_t)((lane >> 4) << 4);
    const int      m4     = lane >> 3;
    const uint32_t b_row4 = (uint32_t)(wn * 56 + ((m4 >> 1) << 3) + (lane & 7));
    const uint32_t b_coff4= (uint32_t)((m4 & 1) << 4);
    const uint32_t b_row2 = (uint32_t)(wn * 56 + 48 + (lane & 7));
    const uint32_t b_coff2= (uint32_t)(((lane >> 3) & 1) << 4);

    #pragma unroll 1
    for (int np = 0; np < 2; np++) {
        __syncthreads();

        auto stageA = [&](int s, int kc) {
            char* base = smem + OFF_A + s * ASZ;
            #pragma unroll
            for (int it = 0; it < 4; it++) {       // 1024 cp16
                int idx = it * 256 + tid;
                int row = idx >> 3, ch = idx & 7;
                cp16(base + row * PITCH + ch * 16,
                     w1h + (size_t)(rbase + row) * C_ + kc + ch * 8, 16);
            }
        };
        auto stageB = [&](int s, int kc) {
            char* base = smem + OFF_B + s * BSZ;
            #pragma unroll
            for (int it = 0; it < 4; it++) {       // 896 cp16
                int idx = it * 256 + tid;
                if (idx < 896) {
                    int row = idx >> 3, ch = idx & 7;
                    int p = np * NPW + row;
                    int ok = (p < P_);
                    const __half* src = xh + (size_t)(ok ? p : 0) * C_ + kc + ch * 8;
                    cp16(base + row * PITCH + ch * 16, src, ok ? 16 : 0);
                }
            }
        };

        stageA(0, 0);  stageB(0, 0);  cp_commit();
        stageA(1, KC); stageB(1, KC); cp_commit();

        float d[2][7][4];
        #pragma unroll
        for (int mt = 0; mt < 2; mt++)
            #pragma unroll
            for (int nt = 0; nt < 7; nt++)
                #pragma unroll
                for (int j = 0; j < 4; j++) d[mt][nt][j] = 0.f;

        #pragma unroll 1
        for (int kci = 0; kci < NKC; kci++) {
            if (kci + 1 < NKC) cp_wait1(); else cp_wait0();
            __syncthreads();

            if (kci + 2 < NKC) {
                int nb = (kci + 2) % 3;
                stageA(nb, (kci + 2) * KC);
                stageB(nb, (kci + 2) * KC);
                cp_commit();
            }

            const uint32_t abase = sbase + OFF_A + (kci % 3) * ASZ;
            const uint32_t bbase = sbase + OFF_B + (kci % 3) * BSZ;

            #pragma unroll
            for (int kk = 0; kk < 4; kk++) {
                const uint32_t kb = (uint32_t)(kk * 32);

                uint32_t a[2][4];
                #pragma unroll
                for (int mt = 0; mt < 2; mt++)
                    ldsm_x4(a[mt][0], a[mt][1], a[mt][2], a[mt][3],
                            abase + (a_row + mt * 16) * PITCH + kb + a_coff);

                uint32_t bb[7][2];
                #pragma unroll
                for (int ntp = 0; ntp < 3; ntp++)
                    ldsm_x4(bb[2 * ntp][0], bb[2 * ntp][1],
                            bb[2 * ntp + 1][0], bb[2 * ntp + 1][1],
                            bbase + (b_row4 + ntp * 16) * PITCH + kb + b_coff4);
                ldsm_x2(bb[6][0], bb[6][1],
                        bbase + b_row2 * PITCH + kb + b_coff2);

                #pragma unroll
                for (int mt = 0; mt < 2; mt++)
                    #pragma unroll
                    for (int nt = 0; nt < 7; nt++)
                        mma_f16(d[mt][nt][0], d[mt][nt][1], d[mt][nt][2], d[mt][nt][3],
                                a[mt][0], a[mt][1], a[mt][2], a[mt][3],
                                bb[nt][0], bb[nt][1]);
            }
        }

        // epilogue
        const int pbase = np * NPW + wn * 56 + (lane & 3) * 2;
        #pragma unroll
        for (int mt = 0; mt < 2; mt++) {
            const int rl0 = wm * 32 + mt * 16 + (lane >> 2);
            const int rl1 = rl0 + 8;
            const float s0c = sc[rl0], b0c = bi[rl0];
            const float s1c = sc[rl1], b1c = bi[rl1];
            float acc0 = 0.f, acc1 = 0.f;
            #pragma unroll
            for (int nt = 0; nt < 7; nt++) {
                #pragma unroll
                for (int jj = 0; jj < 2; jj++) {
                    int p = pbase + nt * 8 + jj;
                    if (p < P_) {
                        float h0 = d[mt][nt][jj] * s0c + b0c;
                        acc0 += h0 * fminf(fmaxf(h0 + 3.f, 0.f), 6.f) * (1.f / 6.f);
                        float h1 = d[mt][nt][2 + jj] * s1c + b1c;
                        acc1 += h1 * fminf(fmaxf(h1 + 3.f, 0.f), 6.f) * (1.f / 6.f);
                    }
                }
            }
            acc0 += __shfl_xor_sync(0xFFFFFFFFu, acc0, 1);
            acc0 += __shfl_xor_sync(0xFFFFFFFFu, acc0, 2);
            acc1 += __shfl_xor_sync(0xFFFFFFFFu, acc1, 1);
            acc1 += __shfl_xor_sync(0xFFFFFFFFu, acc1, 2);
            if ((lane & 3) == 0) {
                part[(np * 2 + wn) * 128 + rl0] += acc0;
                part[(np * 2 + wn) * 128 + rl1] += acc1;
            }
        }
    }

    __syncthreads();
    if (tid < 128)
        g_hmean[b * R_ + rbase + tid] = (part[tid] + part[128 + tid] +
                                         part[256 + tid] + part[384 + tid]) * (1.f / (float)P_);
}

// ============================================================================
// Kernel B: logits = hmean @ w2^T ; BN2 ; sigmoid ; ROI coords
// ============================================================================
__global__ void kernelB(const float* __restrict__ w2, const float* __restrict__ g2,
                        const float* __restrict__ b2, const float* __restrict__ m2,
                        const float* __restrict__ v2) {
    const int b = blockIdx.x;
    const int lane = threadIdx.x;
    const float* h = g_hmean + b * R_;

    float lg[6];
    #pragma unroll
    for (int j = 0; j < 6; j++) {
        float s = 0.f;
        #pragma unroll
        for (int r = lane; r < R_; r += 32) s += h[r] * w2[j * R_ + r];
        #pragma unroll
        for (int off = 16; off; off >>= 1) s += __shfl_xor_sync(0xFFFFFFFFu, s, off);
        lg[j] = s;
    }
    if (lane < 6) {
        const int j = lane;
        float sf = g2[j] * rsqrtf(v2[j] + EPSV);
        float l  = (lg[j] - m2[j]) * sf + b2[j];
        float sig = 1.f / (1.f + expf(-l));
        const float SC[3] = {7.f, 7.f, 4.f};
        float outv = (j < 3) ? (0.5f * sig * SC[j])
                             : ((1.f - 0.5f * sig) * SC[j - 3]);
        g_coords[b * 6 + j] = outv;
    }
}

// ============================================================================
// Kernel C: ROI align 3D from g_xh. Block = (64-ch tile, batch), 256 thr.
// fp16 tile xs[p][64], precomputed tap tables, warp = output point,
// lane = 2 channels. Dual accumulators break the FFMA dependency chain.
// ============================================================================
__global__ void __launch_bounds__(256)
kernelC(float* __restrict__ out) {
    __shared__ __half xs[P_ * 64];       // 25088 B
    __shared__ float  obuf[75 * 66];     // 19800 B
    __shared__ float  w8[75 * 8];        // 2400 B
    __shared__ short  idx8[75 * 8];      // 1200 B

    const int tid  = threadIdx.x;
    const int lane = tid & 31;
    const int warp = tid >> 5;
    const int b    = blockIdx.y;
    const int cc   = blockIdx.x * 64;

    const __half* xh = g_xh + (size_t)b * P_ * C_;

    for (int i = tid; i < P_ * 8; i += 256) {
        int p = i >> 3, q = i & 7;
        uint4 v = reinterpret_cast<const uint4*>(xh + (size_t)p * C_ + cc)[q];
        *reinterpret_cast<uint4*>(xs + p * 64 + q * 8) = v;
    }

    if (tid < 75) {
        const int ot = tid / 25, rr = tid % 25;
        const int oy = rr / 5,   ox = rr - oy * 5;

        float cs[6];
        #pragma unroll
        for (int j = 0; j < 6; j++) cs[j] = g_coords[b * 6 + j];

        auto prep = [&](int axis, int i, int n, float size,
                        int& lo, int& hi, float& w0, float& w1) {
            float s = cs[axis], e = cs[3 + axis];
            float bin = (e - s) / (float)n;
            float c = s + ((float)i + 0.5f) * bin;
            float valid = (c >= -1.f && c <= size) ? 1.f : 0.f;
            c = fminf(fmaxf(c, 0.f), size - 1.f);
            lo = (int)floorf(c);
            hi = min(lo + 1, (int)size - 1);
            float f = c - (float)lo;
            w0 = (1.f - f) * valid;
            w1 = f * valid;
        };

        int xl, xh2, yl, yh2, tl, th2;
        float xw0, xw1, yw0, yw1, tw0, tw1;
        prep(0, ox, 5, 7.f, xl, xh2, xw0, xw1);
        prep(1, oy, 5, 7.f, yl, yh2, yw0, yw1);
        prep(2, ot, 3, 4.f, tl, th2, tw0, tw1);

        #pragma unroll
        for (int k = 0; k < 8; k++) {
            int ti = (k & 4) ? th2 : tl;  float tw = (k & 4) ? tw1 : tw0;
            int yi = (k & 2) ? yh2 : yl;  float yw = (k & 2) ? yw1 : yw0;
            int xi = (k & 1) ? xh2 : xl;  float xw = (k & 1) ? xw1 : xw0;
            w8[tid * 8 + k]   = tw * yw * xw;
            idx8[tid * 8 + k] = (short)(ti * 49 + yi * 7 + xi);
        }
    }
    __syncthreads();

    // gather: warp owns o; lane = channel pair. Even/odd taps accumulate
    // into independent registers (halved dependency chain).
    #pragma unroll 1
    for (int o = warp; o < 75; o += 8) {
        float ax0 = 0.f, ay0 = 0.f, ax1 = 0.f, ay1 = 0.f;
        #pragma unroll
        for (int k = 0; k < 8; k += 2) {
            float w0  = w8[o * 8 + k];
            int   id0 = idx8[o * 8 + k];
            float w1  = w8[o * 8 + k + 1];
            int   id1 = idx8[o * 8 + k + 1];
            __half2 h0 = *reinterpret_cast<const __half2*>(xs + id0 * 64 + lane * 2);
            __half2 h1 = *reinterpret_cast<const __half2*>(xs + id1 * 64 + lane * 2);
            float2 f0 = __half22float2(h0);
            float2 f1 = __half22float2(h1);
            ax0 += w0 * f0.x;  ay0 += w0 * f0.y;
            ax1 += w1 * f1.x;  ay1 += w1 * f1.y;
        }
        *reinterpret_cast<float2*>(obuf + o * 66 + lane * 2) =
            make_float2(ax0 + ax1, ay0 + ay1);
    }
    __syncthreads();

    // write-out: out index is linear in i; track (c,o) incrementally (no div)
    {
        float* ob = out + ((size_t)(b * C_) + cc) * 75;
        int c = tid / 75;
        int o = tid - c * 75;
        for (int i = tid; i < 64 * 75; i += 256) {
            ob[i] = obuf[o * 66 + c];
            c += 3; o += 31;
            if (o >= 75) { o -= 75; c++; }
        }
    }
}

// ============================================================================
extern "C" void kernel_launch(void* const* d_in, const int* in_sizes, int n_in,
                              void* d_out, int out_size) {
    const float* x  = (const float*)d_in[0];
    const float* w1 = (const float*)d_in[1];
    const float* g1 = (const float*)d_in[2];
    const float* b1 = (const float*)d_in[3];
    const float* m1 = (const float*)d_in[4];
    const float* v1 = (const float*)d_in[5];
    const float* w2 = (const float*)d_in[6];
    const float* g2 = (const float*)d_in[7];
    const float* b2 = (const float*)d_in[8];
    const float* m2 = (const float*)d_in[9];
    const float* v2 = (const float*)d_in[10];
    float* out = (float*)d_out;

    cudaFuncSetAttribute(kernelA, cudaFuncAttributeMaxDynamicSharedMemorySize,
                         (int)SMEM_A_TOTAL);

    dim3 gridP(17, B_);
    kernelP<<<gridP, 256>>>(x, w1);
    dim3 gridA(2, B_);
    kernelA<<<gridA, 256, SMEM_A_TOTAL>>>(g1, b1, m1, v1);
    kernelB<<<B_, 32>>>(w2, g2, b2, m2, v2);
    dim3 gridC(C_ / 64, B_);
    kernelC<<<gridC, 256>>>(out);
}

// round 11
// speedup vs baseline: 4.3583x; 1.0239x over previous
#include <cuda_runtime.h>
#include <cuda_fp16.h>
#include <cstdint>
#include <math.h>

// Problem constants
#define B_   128
#define C_   1024
#define R_   256
#define T_   4
#define H_   7
#define W_   7
#define P_   196     // T*H*W
#define EPSV 1e-5f

// ---------------- intermediates (device globals; no allocation allowed) ----
__device__ float  g_hmean[B_ * R_];
__device__ float  g_coords[B_ * 6];
__device__ __half g_xh[(size_t)B_ * P_ * C_];   // x transposed: [b][p][c] fp16
__device__ __half g_w1h[R_ * C_];               // w1 fp16: [r][c]

// ---------------- helpers ---------------------------------------------------
__device__ __forceinline__ void mma_f16(float& d0, float& d1, float& d2, float& d3,
                                        uint32_t a0, uint32_t a1, uint32_t a2, uint32_t a3,
                                        uint32_t b0, uint32_t b1) {
    asm volatile(
        "mma.sync.aligned.m16n8k16.row.col.f32.f16.f16.f32 "
        "{%0,%1,%2,%3}, {%4,%5,%6,%7}, {%8,%9}, {%0,%1,%2,%3};\n"
        : "+f"(d0), "+f"(d1), "+f"(d2), "+f"(d3)
        : "r"(a0), "r"(a1), "r"(a2), "r"(a3), "r"(b0), "r"(b1));
}

__device__ __forceinline__ void ldsm_x4(uint32_t& r0, uint32_t& r1, uint32_t& r2,
                                        uint32_t& r3, uint32_t addr) {
    asm volatile("ldmatrix.sync.aligned.m8n8.x4.shared.b16 {%0,%1,%2,%3}, [%4];"
                 : "=r"(r0), "=r"(r1), "=r"(r2), "=r"(r3) : "r"(addr));
}
__device__ __forceinline__ void ldsm_x2(uint32_t& r0, uint32_t& r1, uint32_t addr) {
    asm volatile("ldmatrix.sync.aligned.m8n8.x2.shared.b16 {%0,%1}, [%2];"
                 : "=r"(r0), "=r"(r1) : "r"(addr));
}

__device__ __forceinline__ void cp16(void* smem_dst, const void* gsrc, int srcbytes) {
    uint32_t s = (uint32_t)__cvta_generic_to_shared(smem_dst);
    asm volatile("cp.async.ca.shared.global [%0], [%1], 16, %2;\n"
                 :: "r"(s), "l"(gsrc), "r"(srcbytes));
}
__device__ __forceinline__ void cp_commit() { asm volatile("cp.async.commit_group;\n"); }
__device__ __forceinline__ void cp_wait0()  { asm volatile("cp.async.wait_group 0;\n"); }
__device__ __forceinline__ void cp_wait1()  { asm volatile("cp.async.wait_group 1;\n"); }

// ============================================================================
// Kernel P: blockIdx.x < 16 : transpose+convert x[b][c][p] f32 -> g_xh[b][p][c]
//           blockIdx.x ==16 : convert w1 -> g_w1h (2 rows per blockIdx.y)
// ============================================================================
__global__ void __launch_bounds__(256)
kernelP(const float* __restrict__ x, const float* __restrict__ w1) {
    const int tid = threadIdx.x;
    const int b   = blockIdx.y;

    if (blockIdx.x == 16) {   // w1 convert: rows [2b, 2b+2)
        const int e0 = b * 2048;
        #pragma unroll
        for (int it = 0; it < 2; it++) {
            int idx = it * 256 + tid;
            float4 v = reinterpret_cast<const float4*>(w1 + e0)[idx];
            __half2 h0 = __floats2half2_rn(v.x, v.y);
            __half2 h1 = __floats2half2_rn(v.z, v.w);
            uint2 u;
            u.x = *reinterpret_cast<uint32_t*>(&h0);
            u.y = *reinterpret_cast<uint32_t*>(&h1);
            reinterpret_cast<uint2*>(g_w1h + e0)[idx] = u;
        }
        return;
    }

    __shared__ unsigned short xs[64 * 202];
    const int c0 = blockIdx.x * 64;

    for (int idx = tid; idx < 64 * 49; idx += 256) {
        int c = idx / 49, q = idx - c * 49;
        float4 v = reinterpret_cast<const float4*>(
                       x + ((size_t)b * C_ + c0 + c) * P_)[q];
        unsigned short* dst = xs + c * 202 + q * 4;
        dst[0] = __half_as_ushort(__float2half_rn(v.x));
        dst[1] = __half_as_ushort(__float2half_rn(v.y));
        dst[2] = __half_as_ushort(__float2half_rn(v.z));
        dst[3] = __half_as_ushort(__float2half_rn(v.w));
    }
    __syncthreads();

    uint32_t* outu = reinterpret_cast<uint32_t*>(g_xh);
    for (int idx = tid; idx < P_ * 32; idx += 256) {
        int p = idx >> 5, ch = idx & 31;
        uint32_t lo = xs[(2 * ch    ) * 202 + p];
        uint32_t hi = xs[(2 * ch + 1) * 202 + p];
        outu[((size_t)b * P_ + p) * (C_ / 2) + (c0 >> 1) + ch] = lo | (hi << 16);
    }
}

// ============================================================================
// Kernel A: GEMM  H[r,p] = sum_c w1[r,c] * x[b,c,p]   (fp16 HMMA m16n8k16)
// fused BN-affine + hardswish + mean over p  ->  g_hmean[b][r]
// CTA = (mhalf, batch): 128 r rows x 196 p.
// Pass 0: cols [0,112), warp tiles 56/56 (NT=7/7)
// Pass 1: cols [112,200), warp tiles 48/40 (NT=6/5) -> 200 total n8 (was 224)
// 256 threads = 8 warps (4M x 2N). KC=64, 3-stage cp.async, ldmatrix frags.
// ============================================================================
#define KC      64
#define NKC     16     // 1024/64
#define PITCH   144    // row pitch bytes (36 words: LDSM phases cover all banks)
#define ASZ     18432  // 128 rows * 144 B
#define BSZ     16128  // 112 rows * 144 B (pass0 max rows)

// smem byte offsets
#define OFF_A    0
#define OFF_B    (3 * ASZ)                   // 55296
#define OFF_PART (OFF_B + 3 * BSZ)           // 103680 (512 f32)
#define OFF_SC   (OFF_PART + 2048)           // 105728 (128 f32)
#define OFF_BI   (OFF_SC + 512)              // 106240 (128 f32)
#define SMEM_A_TOTAL (OFF_BI + 512)          // 106752 B

// one K=64 chunk of HMMA work for a warp with NT n8-tiles
template<int NT>
__device__ __forceinline__ void mma_chunk(
    uint32_t abase, uint32_t bwbase, float d[2][7][4],
    uint32_t a_row, uint32_t a_coff,
    uint32_t rb4, uint32_t b_coff4, uint32_t rb2, uint32_t b_coff2) {
    #pragma unroll
    for (int kk = 0; kk < 4; kk++) {
        const uint32_t kb = (uint32_t)(kk * 32);

        uint32_t a[2][4];
        #pragma unroll
        for (int mt = 0; mt < 2; mt++)
            ldsm_x4(a[mt][0], a[mt][1], a[mt][2], a[mt][3],
                    abase + (a_row + mt * 16) * PITCH + kb + a_coff);

        uint32_t bb[7][2];
        constexpr int NP4 = NT / 2;
        #pragma unroll
        for (int ntp = 0; ntp < NP4; ntp++)
            ldsm_x4(bb[2 * ntp][0], bb[2 * ntp][1],
                    bb[2 * ntp + 1][0], bb[2 * ntp + 1][1],
                    bwbase + (rb4 + ntp * 16) * PITCH + kb + b_coff4);
        if constexpr (NT & 1)
            ldsm_x2(bb[NT - 1][0], bb[NT - 1][1],
                    bwbase + (rb2 + (NT / 2) * 16) * PITCH + kb + b_coff2);

        #pragma unroll
        for (int mt = 0; mt < 2; mt++)
            #pragma unroll
            for (int nt = 0; nt < NT; nt++)
                mma_f16(d[mt][nt][0], d[mt][nt][1], d[mt][nt][2], d[mt][nt][3],
                        a[mt][0], a[mt][1], a[mt][2], a[mt][3],
                        bb[nt][0], bb[nt][1]);
    }
}

__global__ void __launch_bounds__(256, 2)
kernelA(const float* __restrict__ g1, const float* __restrict__ b1,
        const float* __restrict__ m1, const float* __restrict__ v1) {
    extern __shared__ __align__(16) char smem[];
    float* part = reinterpret_cast<float*>(smem + OFF_PART);
    float* sc   = reinterpret_cast<float*>(smem + OFF_SC);
    float* bi   = reinterpret_cast<float*>(smem + OFF_BI);
    const uint32_t sbase = (uint32_t)__cvta_generic_to_shared(smem);

    const int mh   = blockIdx.x;
    const int b    = blockIdx.y;
    const int tid  = threadIdx.x;
    const int lane = tid & 31;
    const int warp = tid >> 5;
    const int wm   = warp >> 1;
    const int wn   = warp & 1;
    const int rbase = mh * 128;

    part[tid]       = 0.f;
    part[tid + 256] = 0.f;
    if (tid < 128) {
        int r = rbase + tid;
        float s = g1[r] * rsqrtf(v1[r] + EPSV);
        sc[tid] = s;
        bi[tid] = b1[r] - m1[r] * s;
    }

    const __half* w1h = g_w1h;
    const __half* xh  = g_xh + (size_t)b * P_ * C_;

    // ldmatrix lane-static address components (warp-tile-relative)
    const uint32_t a_row  = (uint32_t)(wm * 32 + (lane & 15));
    const uint32_t a_coff = (uint32_t)((lane >> 4) << 4);
    const int      m4     = lane >> 3;
    const uint32_t rb4    = (uint32_t)(((m4 >> 1) << 3) + (lane & 7));
    const uint32_t b_coff4= (uint32_t)((m4 & 1) << 4);
    const uint32_t rb2    = (uint32_t)(lane & 7);
    const uint32_t b_coff2= (uint32_t)(((lane >> 3) & 1) << 4);

    #pragma unroll 1
    for (int np = 0; np < 2; np++) {
        __syncthreads();

        const int pcol0 = (np == 0) ? 0 : 112;      // global col base of pass
        const int blim  = (np == 0) ? 896 : 704;    // staged rows * 8 (112/88)
        const int wnoff = (np == 0) ? wn * 56 : wn * 48;  // warp col offset

        auto stageA = [&](int s, int kc) {
            char* base = smem + OFF_A + s * ASZ;
            #pragma unroll
            for (int it = 0; it < 4; it++) {       // 1024 cp16
                int idx = it * 256 + tid;
                int row = idx >> 3, ch = idx & 7;
                cp16(base + row * PITCH + ch * 16,
                     w1h + (size_t)(rbase + row) * C_ + kc + ch * 8, 16);
            }
        };
        auto stageB = [&](int s, int kc) {
            char* base = smem + OFF_B + s * BSZ;
            #pragma unroll
            for (int it = 0; it < 4; it++) {
                int idx = it * 256 + tid;
                if (idx < blim) {
                    int row = idx >> 3, ch = idx & 7;
                    int p = pcol0 + row;
                    int ok = (p < P_);
                    const __half* src = xh + (size_t)(ok ? p : 0) * C_ + kc + ch * 8;
                    cp16(base + row * PITCH + ch * 16, src, ok ? 16 : 0);
                }
            }
        };

        stageA(0, 0);  stageB(0, 0);  cp_commit();
        stageA(1, KC); stageB(1, KC); cp_commit();

        float d[2][7][4];
        #pragma unroll
        for (int mt = 0; mt < 2; mt++)
            #pragma unroll
            for (int nt = 0; nt < 7; nt++)
                #pragma unroll
                for (int j = 0; j < 4; j++) d[mt][nt][j] = 0.f;

        #pragma unroll 1
        for (int kci = 0; kci < NKC; kci++) {
            if (kci + 1 < NKC) cp_wait1(); else cp_wait0();
            __syncthreads();

            if (kci + 2 < NKC) {
                int nb = (kci + 2) % 3;
                stageA(nb, (kci + 2) * KC);
                stageB(nb, (kci + 2) * KC);
                cp_commit();
            }

            const uint32_t abase  = sbase + OFF_A + (kci % 3) * ASZ;
            const uint32_t bwbase = sbase + OFF_B + (kci % 3) * BSZ
                                  + (uint32_t)wnoff * PITCH;

            if (np == 0)
                mma_chunk<7>(abase, bwbase, d, a_row, a_coff, rb4, b_coff4, rb2, b_coff2);
            else if (wn == 0)
                mma_chunk<6>(abase, bwbase, d, a_row, a_coff, rb4, b_coff4, rb2, b_coff2);
            else
                mma_chunk<5>(abase, bwbase, d, a_row, a_coff, rb4, b_coff4, rb2, b_coff2);
        }

        // epilogue: BN affine + hardswish + per-row partial sums
        const int ntmax = (np == 0) ? 7 : (wn == 0 ? 6 : 5);
        const int pbase = pcol0 + wnoff + (lane & 3) * 2;
        #pragma unroll
        for (int mt = 0; mt < 2; mt++) {
            const int rl0 = wm * 32 + mt * 16 + (lane >> 2);
            const int rl1 = rl0 + 8;
            const float s0c = sc[rl0], b0c = bi[rl0];
            const float s1c = sc[rl1], b1c = bi[rl1];
            float acc0 = 0.f, acc1 = 0.f;
            #pragma unroll
            for (int nt = 0; nt < 7; nt++) {
                #pragma unroll
                for (int jj = 0; jj < 2; jj++) {
                    int p = pbase + nt * 8 + jj;
                    if (nt < ntmax && p < P_) {
                        float h0 = d[mt][nt][jj] * s0c + b0c;
                        acc0 += h0 * fminf(fmaxf(h0 + 3.f, 0.f), 6.f) * (1.f / 6.f);
                        float h1 = d[mt][nt][2 + jj] * s1c + b1c;
                        acc1 += h1 * fminf(fmaxf(h1 + 3.f, 0.f), 6.f) * (1.f / 6.f);
                    }
                }
            }
            acc0 += __shfl_xor_sync(0xFFFFFFFFu, acc0, 1);
            acc0 += __shfl_xor_sync(0xFFFFFFFFu, acc0, 2);
            acc1 += __shfl_xor_sync(0xFFFFFFFFu, acc1, 1);
            acc1 += __shfl_xor_sync(0xFFFFFFFFu, acc1, 2);
            if ((lane & 3) == 0) {
                part[(np * 2 + wn) * 128 + rl0] += acc0;
                part[(np * 2 + wn) * 128 + rl1] += acc1;
            }
        }
    }

    __syncthreads();
    if (tid < 128)
        g_hmean[b * R_ + rbase + tid] = (part[tid] + part[128 + tid] +
                                         part[256 + tid] + part[384 + tid]) * (1.f / (float)P_);
}

// ============================================================================
// Kernel B: logits = hmean @ w2^T ; BN2 ; sigmoid ; ROI coords
// ============================================================================
__global__ void kernelB(const float* __restrict__ w2, const float* __restrict__ g2,
                        const float* __restrict__ b2, const float* __restrict__ m2,
                        const float* __restrict__ v2) {
    const int b = blockIdx.x;
    const int lane = threadIdx.x;
    const float* h = g_hmean + b * R_;

    float lg[6];
    #pragma unroll
    for (int j = 0; j < 6; j++) {
        float s = 0.f;
        #pragma unroll
        for (int r = lane; r < R_; r += 32) s += h[r] * w2[j * R_ + r];
        #pragma unroll
        for (int off = 16; off; off >>= 1) s += __shfl_xor_sync(0xFFFFFFFFu, s, off);
        lg[j] = s;
    }
    if (lane < 6) {
        const int j = lane;
        float sf = g2[j] * rsqrtf(v2[j] + EPSV);
        float l  = (lg[j] - m2[j]) * sf + b2[j];
        float sig = 1.f / (1.f + expf(-l));
        const float SC[3] = {7.f, 7.f, 4.f};
        float outv = (j < 3) ? (0.5f * sig * SC[j])
                             : ((1.f - 0.5f * sig) * SC[j - 3]);
        g_coords[b * 6 + j] = outv;
    }
}

// ============================================================================
// Kernel C: ROI align 3D from g_xh. Block = (64-ch tile, batch), 256 thr.
// cp.async tile staging overlapped with tap-table computation.
// fp16 obuf (smem 38.6KB -> 5 CTAs/SM).
// ============================================================================
__global__ void __launch_bounds__(256)
kernelC(float* __restrict__ out) {
    __shared__ __half xs[P_ * 64];       // 25088 B
    __shared__ __half obuf[75 * 66];     // 9900 B
    __shared__ float  w8[75 * 8];        // 2400 B
    __shared__ short  idx8[75 * 8];      // 1200 B

    const int tid  = threadIdx.x;
    const int lane = tid & 31;
    const int warp = tid >> 5;
    const int b    = blockIdx.y;
    const int cc   = blockIdx.x * 64;

    const __half* xh = g_xh + (size_t)b * P_ * C_;

    // async tile stage: 1568 cp16 (overlaps with table computation below)
    #pragma unroll
    for (int it = 0; it < 7; it++) {
        int i = it * 256 + tid;
        if (i < P_ * 8) {
            int p = i >> 3, q = i & 7;
            cp16(xs + p * 64 + q * 8, xh + (size_t)p * C_ + cc + q * 8, 16);
        }
    }
    cp_commit();

    if (tid < 75) {
        const int ot = tid / 25, rr = tid % 25;
        const int oy = rr / 5,   ox = rr - oy * 5;

        float cs[6];
        #pragma unroll
        for (int j = 0; j < 6; j++) cs[j] = g_coords[b * 6 + j];

        auto prep = [&](int axis, int i, int n, float size,
                        int& lo, int& hi, float& w0, float& w1) {
            float s = cs[axis], e = cs[3 + axis];
            float bin = (e - s) / (float)n;
            float c = s + ((float)i + 0.5f) * bin;
            float valid = (c >= -1.f && c <= size) ? 1.f : 0.f;
            c = fminf(fmaxf(c, 0.f), size - 1.f);
            lo = (int)floorf(c);
            hi = min(lo + 1, (int)size - 1);
            float f = c - (float)lo;
            w0 = (1.f - f) * valid;
            w1 = f * valid;
        };

        int xl, xh2, yl, yh2, tl, th2;
        float xw0, xw1, yw0, yw1, tw0, tw1;
        prep(0, ox, 5, 7.f, xl, xh2, xw0, xw1);
        prep(1, oy, 5, 7.f, yl, yh2, yw0, yw1);
        prep(2, ot, 3, 4.f, tl, th2, tw0, tw1);

        #pragma unroll
        for (int k = 0; k < 8; k++) {
            int ti = (k & 4) ? th2 : tl;  float tw = (k & 4) ? tw1 : tw0;
            int yi = (k & 2) ? yh2 : yl;  float yw = (k & 2) ? yw1 : yw0;
            int xi = (k & 1) ? xh2 : xl;  float xw = (k & 1) ? xw1 : xw0;
            w8[tid * 8 + k]   = tw * yw * xw;
            idx8[tid * 8 + k] = (short)(ti * 49 + yi * 7 + xi);
        }
    }
    cp_wait0();
    __syncthreads();

    // gather: warp owns o; lane = channel pair. Even/odd taps accumulate
    // into independent registers (halved dependency chain).
    #pragma unroll 1
    for (int o = warp; o < 75; o += 8) {
        float ax0 = 0.f, ay0 = 0.f, ax1 = 0.f, ay1 = 0.f;
        #pragma unroll
        for (int k = 0; k < 8; k += 2) {
            float w0  = w8[o * 8 + k];
            int   id0 = idx8[o * 8 + k];
            float w1  = w8[o * 8 + k + 1];
            int   id1 = idx8[o * 8 + k + 1];
            __half2 h0 = *reinterpret_cast<const __half2*>(xs + id0 * 64 + lane * 2);
            __half2 h1 = *reinterpret_cast<const __half2*>(xs + id1 * 64 + lane * 2);
            float2 f0 = __half22float2(h0);
            float2 f1 = __half22float2(h1);
            ax0 += w0 * f0.x;  ay0 += w0 * f0.y;
            ax1 += w1 * f1.x;  ay1 += w1 * f1.y;
        }
        __half2 hv = __floats2half2_rn(ax0 + ax1, ay0 + ay1);
        *reinterpret_cast<__half2*>(obuf + o * 66 + lane * 2) = hv;
    }
    __syncthreads();

    // write-out: out index linear in i; (c,o) tracked incrementally (no div)
    {
        float* ob = out + ((size_t)(b * C_) + cc) * 75;
        int c = tid / 75;
        int o = tid - c * 75;
        for (int i = tid; i < 64 * 75; i += 256) {
            ob[i] = __half2float(obuf[o * 66 + c]);
            c += 3; o += 31;
            if (o >= 75) { o -= 75; c++; }
        }
    }
}

// ============================================================================
extern "C" void kernel_launch(void* const* d_in, const int* in_sizes, int n_in,
                              void* d_out, int out_size) {
    const float* x  = (const float*)d_in[0];
    const float* w1 = (const float*)d_in[1];
    const float* g1 = (const float*)d_in[2];
    const float* b1 = (const float*)d_in[3];
    const float* m1 = (const float*)d_in[4];
    const float* v1 = (const float*)d_in[5];
    const float* w2 = (const float*)d_in[6];
    const float* g2 = (const float*)d_in[7];
    const float* b2 = (const float*)d_in[8];
    const float* m2 = (const float*)d_in[9];
    const float* v2 = (const float*)d_in[10];
    float* out = (float*)d_out;

    cudaFuncSetAttribute(kernelA, cudaFuncAttributeMaxDynamicSharedMemorySize,
                         (int)SMEM_A_TOTAL);

    dim3 gridP(17, B_);
    kernelP<<<gridP, 256>>>(x, w1);
    dim3 gridA(2, B_);
    kernelA<<<gridA, 256, SMEM_A_TOTAL>>>(g1, b1, m1, v1);
    kernelB<<<B_, 32>>>(w2, g2, b2, m2, v2);
    dim3 gridC(C_ / 64, B_);
    kernelC<<<gridC, 256>>>(out);
}